// round 10
// baseline (speedup 1.0000x reference)
#include <cuda_runtime.h>
#include <cuda_bf16.h>
#include <mma.h>
#include <cstdint>

using namespace nvcuda;

#define Nn 40000
#define Ee 640000
#define ET 680000   /* Ee + Nn self loops */
#define HIDc 128
#define H1c 4
#define D1 512      /* H1*HID */
#define IND 5
#define EDD 11
#define NEG 0.2f

#define EAP_BLOCKS 640
#define EAP_ROWS 1000
#define CAP2 96

#define MROWS 40064          /* 313 * 128, padded M */
#define SC_BLOCKS 157        /* ceil(40000/256) scan blocks */
#define N1_BLOCKS 1250       /* node1 blocks (Nn*8/256) */

/* k_init block ranges */
#define IB_EAP  640
#define IB_W2   256
#define IB_W1E  64           /* W1 expanded block-diagonal -> bf16 [32][512] */
#define IB_CNT  2657         /* ceil(680000/256) */
#define IB_US2  128          /* 1024 warp-outputs: us2/ud2 */
#define IB_MISC 12           /* 95 warp-outputs: aev1,aev2,us1,ud1 */
#define IB_TOTAL (IB_EAP + IB_W2 + IB_W1E + IB_CNT + IB_US2 + IB_MISC)

// ---------------- scratch (device globals; no allocation allowed) ----------
__device__ __nv_bfloat16 g_yb[(size_t)MROWS * 32];      // Y rows (padded stay zero)
__device__ __nv_bfloat16 g_W1eb[32 * D1];               // expanded W1, bf16
__device__ uint32_t g_xh2b[(size_t)MROWS * 64];         // bf16x2 packed
__device__ __nv_bfloat16 g_W2b[D1 * HIDc];
__device__ float g_x8[(size_t)Nn * 8];                  // padded x rows (32B)
__device__ float g_as1[Nn * H1c];
__device__ float g_ad1[Nn * H1c];
__device__ float g_as2[Nn];
__device__ float g_ad2[Nn];
__device__ int   g_deg[Nn];
__device__ int   g_rowstart[Nn + 1];
__device__ int   g_cursor[Nn];
__device__ int   g_flag[SC_BLOCKS];
__device__ int   g_aggv[SC_BLOCKS];
__device__ int   g_inclv[SC_BLOCKS];
__device__ float4 g_csr[(size_t)ET * 2];   // AoS: {src,e2,a1_0,a1_1},{a1_2,a1_3,-,-}
__device__ float g_eamean[EDD];
__device__ float g_eapart[EAP_BLOCKS * EDD];
__device__ float g_aev1[H1c * EDD];
__device__ float g_aev2[EDD];
__device__ float g_us1[H1c * IND];
__device__ float g_ud1[H1c * IND];
__device__ float g_us2[D1];
__device__ float g_ud2[D1];

// ---------------- small helpers --------------------------------------------
__device__ __forceinline__ uint32_t smem_u32(const void* p) {
    uint32_t a;
    asm("{ .reg .u64 t; cvta.to.shared.u64 t, %1; cvt.u32.u64 %0, t; }" : "=r"(a) : "l"(p));
    return a;
}
__device__ __forceinline__ void cp_async16(uint32_t dst, const void* src) {
    asm volatile("cp.async.cg.shared.global [%0], [%1], 16;" :: "r"(dst), "l"(src));
}
#define CP_COMMIT() asm volatile("cp.async.commit_group;" ::: "memory")
#define CP_WAIT0()  asm volatile("cp.async.wait_group 0;" ::: "memory")

__device__ __forceinline__ float warp_red(float v) {
#pragma unroll
    for (int off = 16; off > 0; off >>= 1)
        v += __shfl_down_sync(0xffffffffu, v, off);
    return v;
}

__device__ __forceinline__ float warp_dot128(const float* a, const float* b, int lane) {
    float s = 0.f;
#pragma unroll
    for (int c = 0; c < 4; c++) s = fmaf(a[lane + 32 * c], b[lane + 32 * c], s);
    return warp_red(s);
}

// block-wide inclusive scan helper (256 threads)
__device__ __forceinline__ int block_scan_incl(int v, int t, int* total_out) {
    int lane = t & 31, w = t >> 5;
    int sv = v;
#pragma unroll
    for (int off = 1; off < 32; off <<= 1) {
        int nv = __shfl_up_sync(0xffffffffu, sv, off);
        if (lane >= off) sv += nv;
    }
    __shared__ int ws[8];
    __shared__ int wo[8];
    __shared__ int tot;
    if (lane == 31) ws[w] = sv;
    __syncthreads();
    if (t == 0) {
        int run = 0;
#pragma unroll
        for (int k = 0; k < 8; k++) { wo[k] = run; run += ws[k]; }
        tot = run;
    }
    __syncthreads();
    *total_out = tot;
    return sv + wo[w];
}

// ---------------- kernels --------------------------------------------------

// fused init: ea partials | W2->bf16 | W1 expand | degree count | u/aev precompute
__global__ void k_init(const float* __restrict__ ea,  const float* __restrict__ W2,
                       const int*   __restrict__ ei,
                       const float* __restrict__ W1,  const float* __restrict__ We1,
                       const float* __restrict__ We2,
                       const float* __restrict__ as1, const float* __restrict__ ad1,
                       const float* __restrict__ ae1,
                       const float* __restrict__ as2, const float* __restrict__ ad2,
                       const float* __restrict__ ae2) {
    int b = blockIdx.x, t = threadIdx.x;
    if (b < IB_EAP) {
        __shared__ float sm[256 * EDD];
        float loc[EDD];
#pragma unroll
        for (int d = 0; d < EDD; d++) loc[d] = 0.f;
        int r0 = b * EAP_ROWS;
        for (int r = t; r < EAP_ROWS; r += 256) {
            const float* p = ea + (size_t)(r0 + r) * EDD;
#pragma unroll
            for (int d = 0; d < EDD; d++) loc[d] += p[d];
        }
#pragma unroll
        for (int d = 0; d < EDD; d++) sm[t * EDD + d] = loc[d];
        __syncthreads();
        for (int off = 128; off > 0; off >>= 1) {
            if (t < off) {
#pragma unroll
                for (int d = 0; d < EDD; d++) sm[t * EDD + d] += sm[(t + off) * EDD + d];
            }
            __syncthreads();
        }
        if (t < EDD) g_eapart[b * EDD + t] = sm[t];
    } else if (b < IB_EAP + IB_W2) {
        int idx = (b - IB_EAP) * 256 + t;
        g_W2b[idx] = __float2bfloat16(W2[idx]);
    } else if (b < IB_EAP + IB_W2 + IB_W1E) {
        int idx = (b - IB_EAP - IB_W2) * 256 + t;   // 0..16383
        int r = idx >> 9, c = idx & 511;
        float v = 0.f;
        if (r < 20 && (c >> 7) == (r / 5)) v = W1[(r % 5) * D1 + c];
        g_W1eb[idx] = __float2bfloat16(v);
    } else if (b < IB_EAP + IB_W2 + IB_W1E + IB_CNT) {
        int e = (b - IB_EAP - IB_W2 - IB_W1E) * 256 + t;
        if (e < ET) {
            int d = (e < Ee) ? ei[Ee + e] : (e - Ee);
            atomicAdd(&g_deg[d], 1);
        }
    } else if (b < IB_EAP + IB_W2 + IB_W1E + IB_CNT + IB_US2) {
        int g = (b - IB_EAP - IB_W2 - IB_W1E - IB_CNT) * 8 + (t >> 5);
        int lane = t & 31;
        if (g < 512) {
            float s = warp_dot128(W2 + (size_t)g * HIDc, as2, lane);
            if (lane == 0) g_us2[g] = s;
        } else {
            int k = g - 512;
            float s = warp_dot128(W2 + (size_t)k * HIDc, ad2, lane);
            if (lane == 0) g_ud2[k] = s;
        }
    } else {
        int g = (b - IB_EAP - IB_W2 - IB_W1E - IB_CNT - IB_US2) * 8 + (t >> 5);
        int lane = t & 31;
        if (g < 44) {
            int h = g / EDD, d = g % EDD;
            float s = 0.f;
#pragma unroll
            for (int c = 0; c < 4; c++)
                s = fmaf(We1[d * D1 + h * HIDc + lane + 32 * c],
                         ae1[h * HIDc + lane + 32 * c], s);
            s = warp_red(s);
            if (lane == 0) g_aev1[g] = s;
        } else if (g < 55) {
            int d = g - 44;
            float s = warp_dot128(We2 + (size_t)d * HIDc, ae2, lane);
            if (lane == 0) g_aev2[d] = s;
        } else if (g < 75) {
            int o = g - 55, h = o / IND, d = o % IND;
            float s = 0.f;
#pragma unroll
            for (int c = 0; c < 4; c++)
                s = fmaf(W1[d * D1 + h * HIDc + lane + 32 * c],
                         as1[h * HIDc + lane + 32 * c], s);
            s = warp_red(s);
            if (lane == 0) g_us1[o] = s;
        } else if (g < 95) {
            int o = g - 75, h = o / IND, d = o % IND;
            float s = 0.f;
#pragma unroll
            for (int c = 0; c < 4; c++)
                s = fmaf(W1[d * D1 + h * HIDc + lane + 32 * c],
                         ad1[h * HIDc + lane + 32 * c], s);
            s = warp_red(s);
            if (lane == 0) g_ud1[o] = s;
        }
    }
}

// fused: decoupled-lookback scan | eamean | node1
__global__ void k_mid(const float* __restrict__ x) {
    int b = blockIdx.x, t = threadIdx.x;
    if (b < SC_BLOCKS) {
        int i = b * 256 + t;
        int v = (i < Nn) ? g_deg[i] : 0;
        int tot;
        int incl = block_scan_incl(v, t, &tot);
        __shared__ int s_off;
        volatile int* flag = g_flag;
        volatile int* aggv = g_aggv;
        volatile int* inclv = g_inclv;
        if (t == 0) {
            if (b == 0) {
                inclv[0] = tot; __threadfence(); flag[0] = 2;
                s_off = 0;
            } else {
                aggv[b] = tot; __threadfence(); flag[b] = 1;
                int run = 0, j = b - 1;
                while (true) {
                    int f;
                    do { f = flag[j]; } while (f == 0);
                    if (f == 2) { run += inclv[j]; break; }
                    run += aggv[j]; j--;
                }
                inclv[b] = run + tot; __threadfence(); flag[b] = 2;
                s_off = run;
            }
        }
        __syncthreads();
        int r = s_off + incl - v;
        if (i < Nn) { g_rowstart[i] = r; g_cursor[i] = r; }
        if (b == SC_BLOCKS - 1 && t == 255) g_rowstart[Nn] = ET;
    } else if (b == SC_BLOCKS) {
        int w = t >> 5, lane = t & 31;
        for (int col = w; col < EDD; col += 8) {
            float s = 0.f;
            for (int p = lane; p < EAP_BLOCKS; p += 32) s += g_eapart[p * EDD + col];
            s = warp_red(s);
            if (lane == 0) g_eamean[col] = s / (float)Ee;
        }
    } else {
        int idx = (b - SC_BLOCKS - 1) * 256 + t;
        int n = idx >> 3;
        if (n >= Nn) return;
        int r = idx & 7;
        int h = r & 3;
        const float* xp = x + (size_t)n * IND;
        g_x8[(size_t)n * 8 + r] = (r < IND) ? xp[r] : 0.f;
        const float* u = (r < 4) ? (g_us1 + h * IND) : (g_ud1 + h * IND);
        float s = 0.f;
#pragma unroll
        for (int d = 0; d < IND; d++) s += xp[d] * u[d];
        if (r < 4) g_as1[n * H1c + h] = s;
        else       g_ad1[n * H1c + h] = s;
    }
}

// CSR scatter; stores leakyrelu(alpha1) per head + raw e2 dot  (R8 form)
__global__ void k_scatter(const int* __restrict__ ei, const float* __restrict__ ea) {
    int e = blockIdx.x * blockDim.x + threadIdx.x;
    if (e >= ET) return;
    int s, d;
    float v[EDD];
    if (e < Ee) {
        s = ei[e]; d = ei[Ee + e];
        const float* p = ea + (size_t)e * EDD;
#pragma unroll
        for (int k = 0; k < EDD; k++) v[k] = p[k];
    } else {
        s = e - Ee; d = s;
#pragma unroll
        for (int k = 0; k < EDD; k++) v[k] = g_eamean[k];
    }
    int pos = atomicAdd(&g_cursor[d], 1);
    float e2 = 0.f;
#pragma unroll
    for (int k = 0; k < EDD; k++) e2 += v[k] * g_aev2[k];

    float4 asv = *(const float4*)&g_as1[s * H1c];
    float4 adv = *(const float4*)&g_ad1[d * H1c];
    float al[H1c];
#pragma unroll
    for (int h = 0; h < H1c; h++) {
        float ed = 0.f;
#pragma unroll
        for (int k = 0; k < EDD; k++) ed += v[k] * g_aev1[h * EDD + k];
        float a = ((h == 0) ? asv.x : (h == 1) ? asv.y : (h == 2) ? asv.z : asv.w)
                + ((h == 0) ? adv.x : (h == 1) ? adv.y : (h == 2) ? adv.z : adv.w) + ed;
        al[h] = (a > 0.f) ? a : NEG * a;
    }
    g_csr[(size_t)pos * 2]     = make_float4(__int_as_float(s), e2, al[0], al[1]);
    g_csr[(size_t)pos * 2 + 1] = make_float4(al[2], al[3], 0.f, 0.f);
}

// layer-1 softmax + aggregation in input space; emit Y row (ax*inv, bf16).
// One warp per node, no projection epilogue.
__global__ __launch_bounds__(256) void k_agg1() {
    int w = threadIdx.x >> 5;
    int lane = threadIdx.x & 31;
    int n = blockIdx.x * 8 + w;
    if (n >= Nn) return;
    int base = g_rowstart[n];
    int deg  = g_rowstart[n + 1] - base;

    float den[H1c];
    float ax[H1c][IND];
#pragma unroll
    for (int h = 0; h < H1c; h++) {
        den[h] = 0.f;
#pragma unroll
        for (int d = 0; d < IND; d++) ax[h][d] = 0.f;
    }

    for (int i = lane; i < deg; i += 32) {
        float4 fa = g_csr[(size_t)(base + i) * 2];
        float4 fb = g_csr[(size_t)(base + i) * 2 + 1];
        int src = __float_as_int(fa.x);
        float e0 = __expf(fa.z), e1 = __expf(fa.w), e2 = __expf(fb.x), e3 = __expf(fb.y);
        den[0] += e0; den[1] += e1; den[2] += e2; den[3] += e3;
        const float* xp = g_x8 + (size_t)src * 8;
        float4 xv4 = __ldg((const float4*)xp);
        float xv5 = __ldg(xp + 4);
        float xv[IND] = {xv4.x, xv4.y, xv4.z, xv4.w, xv5};
#pragma unroll
        for (int d = 0; d < IND; d++) {
            ax[0][d] = fmaf(e0, xv[d], ax[0][d]);
            ax[1][d] = fmaf(e1, xv[d], ax[1][d]);
            ax[2][d] = fmaf(e2, xv[d], ax[2][d]);
            ax[3][d] = fmaf(e3, xv[d], ax[3][d]);
        }
    }
#pragma unroll
    for (int off = 16; off > 0; off >>= 1) {
#pragma unroll
        for (int h = 0; h < H1c; h++) {
            den[h] += __shfl_xor_sync(0xffffffffu, den[h], off);
#pragma unroll
            for (int d = 0; d < IND; d++)
                ax[h][d] += __shfl_xor_sync(0xffffffffu, ax[h][d], off);
        }
    }
    if (lane < 16) {
        float inv0 = 0.f, inv1 = 0.f;
        int k0 = lane * 2, k1 = k0 + 1;
        float v0 = 0.f, v1 = 0.f;
        if (k0 < 20) { inv0 = 1.f / (den[k0 / 5] + 1e-16f); v0 = ax[k0 / 5][k0 % 5] * inv0; }
        if (k1 < 20) { inv1 = 1.f / (den[k1 / 5] + 1e-16f); v1 = ax[k1 / 5][k1 % 5] * inv1; }
        __nv_bfloat162 bv = __float22bfloat162_rn(make_float2(v0, v1));
        *(__nv_bfloat162*)(g_yb + (size_t)n * 32 + k0) = bv;
    }
}

// Fused two-stage GEMM:
//   stage 1 (per 64-K chunk): h1_chunk = relu(Y @ W1e[:,chunk] + b1) via wmma
//   stage 2: xh2 += h1_chunk @ W2[chunk,:] via wmma
// Also accumulates as2/ad2 = h1 . us2/ud2 in fp32.
#define YS_OFF   0                    /* [128][40] bf16 = 10240 */
#define W1S_OFF  10240                /* 2 x [32][72] bf16 = 9216 */
#define HS_OFF   19456                /* [128][72] f32 = 36864 */
#define AS_OFF   56320                /* [128][72] bf16 = 18432 */
#define BS_OFF   74752                /* 2 x [64][136] bf16 = 34816 */
#define GSM_TOTAL 109568

__global__ __launch_bounds__(256, 2) void k_gemm(const float* __restrict__ b1) {
    extern __shared__ char smc[];
    __nv_bfloat16* Ys  = (__nv_bfloat16*)(smc + YS_OFF);
    __nv_bfloat16* W1s = (__nv_bfloat16*)(smc + W1S_OFF);
    float*         Hs  = (float*)(smc + HS_OFF);
    __nv_bfloat16* As  = (__nv_bfloat16*)(smc + AS_OFF);
    __nv_bfloat16* Bs  = (__nv_bfloat16*)(smc + BS_OFF);
    uint32_t smY  = smem_u32(Ys);
    uint32_t smW1 = smem_u32(W1s);
    uint32_t smB  = smem_u32(Bs);

    int t = threadIdx.x;
    int wid = t >> 5;
    int row0 = blockIdx.x * 128;
    int wm0  = (wid >> 2) * 64;     // 0 or 64
    int wn0  = (wid & 3) * 32;      // main-N: 0,32,64,96
    int wn0m = (wid & 3) * 16;      // mini-N: 0,16,32,48

    wmma::fragment<wmma::accumulator, 16, 16, 16, float> acc[4][2];
#pragma unroll
    for (int m = 0; m < 4; m++)
#pragma unroll
        for (int n = 0; n < 2; n++) wmma::fill_fragment(acc[m][n], 0.f);

    auto load_B = [&](int buf, int k0) {
#pragma unroll
        for (int i = 0; i < 4; i++) {
            int v = i * 256 + t;
            int r = v >> 4, c8 = v & 15;
            cp_async16(smB + (uint32_t)(buf * 8704 + r * 136 + c8 * 8) * 2,
                       g_W2b + (size_t)(k0 + r) * HIDc + c8 * 8);
        }
    };
    auto load_W1 = [&](int buf, int c) {
        int r = t >> 3, c8 = t & 7;
        cp_async16(smW1 + (uint32_t)(buf * 2304 + r * 72 + c8 * 8) * 2,
                   g_W1eb + (size_t)r * D1 + c * 64 + c8 * 8);
    };

    // prologue: Y tile + chunk-0 W1 slice + chunk-0 B
#pragma unroll
    for (int i = 0; i < 2; i++) {
        int v = i * 256 + t;
        int r = v >> 2, c8 = v & 3;
        cp_async16(smY + (uint32_t)(r * 40 + c8 * 8) * 2,
                   g_yb + (size_t)(row0 + r) * 32 + c8 * 8);
    }
    load_W1(0, 0);
    load_B(0, 0);
    CP_COMMIT();

    int er = t >> 1, ec0 = (t & 1) * 32;
    float pS = 0.f, pD = 0.f;

    int buf = 0;
    for (int c = 0; c < 8; c++) {
        CP_WAIT0();
        __syncthreads();            // data ready; prev main-wmma done (As/Hs reusable)
        if (c < 7) {
            load_W1(buf ^ 1, c + 1);
            load_B(buf ^ 1, (c + 1) * 64);
            CP_COMMIT();
        }
        // stage 1: mini wmma  Y[128x32] @ W1e[32x64] -> Hs
        {
            wmma::fragment<wmma::accumulator, 16, 16, 16, float> hacc[4];
#pragma unroll
            for (int m = 0; m < 4; m++) wmma::fill_fragment(hacc[m], 0.f);
#pragma unroll
            for (int kk = 0; kk < 2; kk++) {
                wmma::fragment<wmma::matrix_b, 16, 16, 16, __nv_bfloat16, wmma::row_major> w1f;
                wmma::load_matrix_sync(w1f, W1s + buf * 2304 + kk * 16 * 72 + wn0m, 72);
#pragma unroll
                for (int m = 0; m < 4; m++) {
                    wmma::fragment<wmma::matrix_a, 16, 16, 16, __nv_bfloat16, wmma::row_major> yf;
                    wmma::load_matrix_sync(yf, Ys + (wm0 + m * 16) * 40 + kk * 16, 40);
                    wmma::mma_sync(hacc[m], yf, w1f, hacc[m]);
                }
            }
#pragma unroll
            for (int m = 0; m < 4; m++)
                wmma::store_matrix_sync(Hs + (wm0 + m * 16) * 72 + wn0m, hacc[m], 72,
                                        wmma::mem_row_major);
        }
        __syncthreads();
        // elementwise: bias + relu -> As (bf16); accumulate as2/ad2 partials
        {
            int c0 = c * 64;
#pragma unroll
            for (int j = 0; j < 32; j++) {
                int cc = ec0 + j;
                float v = Hs[er * 72 + cc] + b1[c0 + cc];
                v = (v > 0.f) ? v : 0.f;
                As[er * 72 + cc] = __float2bfloat16(v);
                pS = fmaf(v, g_us2[c0 + cc], pS);
                pD = fmaf(v, g_ud2[c0 + cc], pD);
            }
        }
        __syncthreads();
        // stage 2: main wmma  h1_chunk @ W2_chunk -> acc
#pragma unroll
        for (int kk = 0; kk < 4; kk++) {
            wmma::fragment<wmma::matrix_a, 16, 16, 16, __nv_bfloat16, wmma::row_major> af[4];
            wmma::fragment<wmma::matrix_b, 16, 16, 16, __nv_bfloat16, wmma::row_major> bf[2];
#pragma unroll
            for (int m = 0; m < 4; m++)
                wmma::load_matrix_sync(af[m], As + (wm0 + m * 16) * 72 + kk * 16, 72);
#pragma unroll
            for (int n = 0; n < 2; n++)
                wmma::load_matrix_sync(bf[n], Bs + buf * 8704 + (kk * 16) * 136 + wn0 + n * 16, 136);
#pragma unroll
            for (int m = 0; m < 4; m++)
#pragma unroll
                for (int n = 0; n < 2; n++)
                    wmma::mma_sync(acc[m][n], af[m], bf[n], acc[m][n]);
        }
        buf ^= 1;
    }

    // as2/ad2: combine the two half-row partials
    pS += __shfl_xor_sync(0xffffffffu, pS, 1);
    pD += __shfl_xor_sync(0xffffffffu, pD, 1);
    {
        int row = row0 + er;
        if ((t & 1) == 0 && row < Nn) { g_as2[row] = pS; g_ad2[row] = pD; }
    }
    __syncthreads();

    // stage fp32 C in smem, emit packed bf16x2
    float* Cs = (float*)smc;    // 64KB
#pragma unroll
    for (int m = 0; m < 4; m++)
#pragma unroll
        for (int n = 0; n < 2; n++)
            wmma::store_matrix_sync(Cs + (size_t)(wm0 + m * 16) * 128 + wn0 + n * 16,
                                    acc[m][n], 128, wmma::mem_row_major);
    __syncthreads();
#pragma unroll
    for (int j = 0; j < 32; j++) {
        int idx = j * 256 + t;
        int row = idx >> 6, cp = idx & 63;
        float2 f = *(const float2*)&Cs[row * 128 + cp * 2];
        __nv_bfloat162 bv = __float22bfloat162_rn(f);
        g_xh2b[(size_t)(row0 + row) * 64 + cp] = *(uint32_t*)&bv;
    }
}

// layer-2 softmax + aggregation + final linear + sigmoid, fused per dst.
__global__ __launch_bounds__(128) void k_agg2(const float* __restrict__ b2,
                                              const float* __restrict__ Wfc,
                                              const float* __restrict__ bfc,
                                              float* __restrict__ out) {
    int n = blockIdx.x, t = threadIdx.x;
    int base = g_rowstart[n];
    int deg  = g_rowstart[n + 1] - base;
    __shared__ float s_ex[CAP2];
    __shared__ int   s_src[CAP2];
    __shared__ float s_w[4];
    __shared__ float s_den;
    __shared__ float2 s_half[2][64];
    __shared__ float s_red[2];

    float ad = g_ad2[n];
    float partial = 0.f;
    for (int i = t; i < deg; i += 128) {
        float4 f = g_csr[(size_t)(base + i) * 2];
        int src = __float_as_int(f.x);
        float al = g_as2[src] + ad + f.y;
        al = (al > 0.f) ? al : NEG * al;
        float ex = __expf(al);
        partial += ex;
        if (i < CAP2) { s_ex[i] = ex; s_src[i] = src; }
    }
    for (int off = 16; off > 0; off >>= 1)
        partial += __shfl_down_sync(0xffffffffu, partial, off);
    if ((t & 31) == 0) s_w[t >> 5] = partial;
    __syncthreads();
    if (t == 0) s_den = s_w[0] + s_w[1] + s_w[2] + s_w[3];
    __syncthreads();
    float inv = 1.f / (s_den + 1e-16f);

    int eh = t >> 6, p = t & 63;
    float2 a0 = {0.f, 0.f}, a1 = {0.f, 0.f}, a2 = {0.f, 0.f}, a3 = {0.f, 0.f};

    auto step = [&](int i, float2& a) {
        float ex; int src;
        if (i < CAP2) { ex = s_ex[i]; src = s_src[i]; }
        else {
            float4 f = g_csr[(size_t)(base + i) * 2];
            src = __float_as_int(f.x);
            float al = g_as2[src] + ad + f.y;
            al = (al > 0.f) ? al : NEG * al;
            ex = __expf(al);
        }
        uint32_t raw = g_xh2b[(size_t)src * 64 + p];
        __nv_bfloat162 bv = *(__nv_bfloat162*)&raw;
        float2 fv = __bfloat1622float2(bv);
        a.x = fmaf(ex, fv.x, a.x);
        a.y = fmaf(ex, fv.y, a.y);
    };

    int i = eh;
    for (; i + 6 < deg; i += 8) {
        step(i, a0); step(i + 2, a1); step(i + 4, a2); step(i + 6, a3);
    }
    for (; i < deg; i += 2) step(i, a0);
    a0.x = (a0.x + a1.x) + (a2.x + a3.x);
    a0.y = (a0.y + a1.y) + (a2.y + a3.y);

    s_half[eh][p] = a0;
    __syncthreads();

    if (t < 64) {
        float2 hA = s_half[0][t], hB = s_half[1][t];
        float h0 = (hA.x + hB.x) * inv;
        float h1 = (hA.y + hB.y) * inv;
        float2 bb = *(const float2*)&b2[2 * t];
        h0 += bb.x; h1 += bb.y;
        h0 = (h0 > 0.f) ? h0 : 0.f;
        h1 = (h1 > 0.f) ? h1 : 0.f;
        float2 wf = *(const float2*)&Wfc[2 * t];
        float part = fmaf(h0, wf.x, h1 * wf.y);
        for (int off = 16; off > 0; off >>= 1)
            part += __shfl_down_sync(0xffffffffu, part, off);
        if ((t & 31) == 0) s_red[t >> 5] = part;
    }
    __syncthreads();
    if (t == 0) {
        float z = s_red[0] + s_red[1] + bfc[0];
        out[n] = 1.f / (1.f + __expf(-z));
    }
}

// ---------------- launcher -------------------------------------------------

extern "C" void kernel_launch(void* const* d_in, const int* in_sizes, int n_in,
                              void* d_out, int out_size) {
    const float* x    = (const float*)d_in[0];
    const int*   ei   = (const int*)  d_in[1];
    const float* ea   = (const float*)d_in[2];
    const float* W1   = (const float*)d_in[3];
    const float* We1  = (const float*)d_in[4];
    const float* as1v = (const float*)d_in[5];
    const float* ad1v = (const float*)d_in[6];
    const float* ae1v = (const float*)d_in[7];
    const float* b1   = (const float*)d_in[8];
    const float* W2   = (const float*)d_in[9];
    const float* We2  = (const float*)d_in[10];
    const float* as2v = (const float*)d_in[11];
    const float* ad2v = (const float*)d_in[12];
    const float* ae2v = (const float*)d_in[13];
    const float* b2   = (const float*)d_in[14];
    const float* Wfc  = (const float*)d_in[15];
    const float* bfc  = (const float*)d_in[16];
    float* out = (float*)d_out;

    static void* p_deg = nullptr;
    static void* p_flag = nullptr;
    if (!p_deg) {
        cudaFuncSetAttribute(k_gemm, cudaFuncAttributeMaxDynamicSharedMemorySize, GSM_TOTAL);
        cudaGetSymbolAddress(&p_deg, g_deg);
        cudaGetSymbolAddress(&p_flag, g_flag);
    }

    cudaMemsetAsync(p_deg, 0, Nn * sizeof(int));
    cudaMemsetAsync(p_flag, 0, SC_BLOCKS * sizeof(int));
    k_init<<<IB_TOTAL, 256>>>(ea, W2, ei, W1, We1, We2,
                              as1v, ad1v, ae1v, as2v, ad2v, ae2v);
    k_mid<<<SC_BLOCKS + 1 + N1_BLOCKS, 256>>>(x);
    k_scatter<<<(ET + 255) / 256, 256>>>(ei, ea);
    k_agg1<<<(Nn + 7) / 8, 256>>>();
    k_gemm<<<MROWS / 128, 256, GSM_TOTAL>>>(b1);
    k_agg2<<<Nn, 128>>>(b2, Wfc, bfc, out);
}

// round 11
// speedup vs baseline: 1.1161x; 1.1161x over previous
#include <cuda_runtime.h>
#include <cuda_bf16.h>
#include <mma.h>
#include <cstdint>

using namespace nvcuda;

#define Nn 40000
#define Ee 640000
#define ET 680000   /* Ee + Nn self loops */
#define HIDc 128
#define H1c 4
#define D1 512      /* H1*HID */
#define IND 5
#define EDD 11
#define NEG 0.2f

#define EAP_BLOCKS 640
#define EAP_ROWS 1000
#define CAP2 96

#define MROWS 40064          /* 313 * 128, padded M */
#define SC_BLOCKS 157        /* ceil(40000/256) scan blocks */

/* k_init block ranges */
#define IB_EAP  640
#define IB_W2   256
#define IB_CNT  2657         /* ceil(680000/256) */
#define IB_US2  128          /* 1024 warp-outputs: us2/ud2 */
#define IB_MISC 12           /* 95 warp-outputs: aev1,aev2,us1,ud1 */
#define IB_TOTAL (IB_EAP + IB_W2 + IB_CNT + IB_US2 + IB_MISC)

// ---------------- scratch (device globals; no allocation allowed) ----------
__device__ __nv_bfloat16 g_h1b[(size_t)MROWS * D1];     // padded rows stay zero
__device__ uint32_t g_xh2b[(size_t)MROWS * 64];         // bf16x2 packed
__device__ __nv_bfloat16 g_W2b[D1 * HIDc];
__device__ float g_x8[(size_t)Nn * 8];                  // padded x rows (32B)
__device__ float g_as1[Nn * H1c];
__device__ float g_ad1[Nn * H1c];
__device__ float g_as2[Nn];
__device__ float g_ad2[Nn];
__device__ int   g_deg[Nn];
__device__ int   g_rowstart[Nn + 1];
__device__ int   g_cursor[Nn];
__device__ int   g_flag[SC_BLOCKS];
__device__ int   g_aggv[SC_BLOCKS];
__device__ int   g_inclv[SC_BLOCKS];
__device__ float4 g_csr[(size_t)ET * 2];   // AoS: {src,e2,a1_0,a1_1},{a1_2,a1_3,-,-}
__device__ float g_eamean[EDD];
__device__ float g_eapart[EAP_BLOCKS * EDD];
__device__ float g_aev1[H1c * EDD];
__device__ float g_aev2[EDD];
__device__ float g_us1[H1c * IND];
__device__ float g_ud1[H1c * IND];
__device__ float g_us2[D1];
__device__ float g_ud2[D1];

// ---------------- small helpers --------------------------------------------
__device__ __forceinline__ uint32_t smem_u32(const void* p) {
    uint32_t a;
    asm("{ .reg .u64 t; cvta.to.shared.u64 t, %1; cvt.u32.u64 %0, t; }" : "=r"(a) : "l"(p));
    return a;
}
__device__ __forceinline__ void cp_async16(uint32_t dst, const void* src) {
    asm volatile("cp.async.cg.shared.global [%0], [%1], 16;" :: "r"(dst), "l"(src));
}
#define CP_COMMIT() asm volatile("cp.async.commit_group;" ::: "memory")
#define CP_WAIT1()  asm volatile("cp.async.wait_group 1;" ::: "memory")
#define CP_WAIT0()  asm volatile("cp.async.wait_group 0;" ::: "memory")

__device__ __forceinline__ float warp_red(float v) {
#pragma unroll
    for (int off = 16; off > 0; off >>= 1)
        v += __shfl_down_sync(0xffffffffu, v, off);
    return v;
}

__device__ __forceinline__ float warp_dot128(const float* a, const float* b, int lane) {
    float s = 0.f;
#pragma unroll
    for (int c = 0; c < 4; c++) s = fmaf(a[lane + 32 * c], b[lane + 32 * c], s);
    return warp_red(s);
}

// block-wide inclusive scan helper (256 threads)
__device__ __forceinline__ int block_scan_incl(int v, int t, int* total_out) {
    int lane = t & 31, w = t >> 5;
    int sv = v;
#pragma unroll
    for (int off = 1; off < 32; off <<= 1) {
        int nv = __shfl_up_sync(0xffffffffu, sv, off);
        if (lane >= off) sv += nv;
    }
    __shared__ int ws[8];
    __shared__ int wo[8];
    __shared__ int tot;
    if (lane == 31) ws[w] = sv;
    __syncthreads();
    if (t == 0) {
        int run = 0;
#pragma unroll
        for (int k = 0; k < 8; k++) { wo[k] = run; run += ws[k]; }
        tot = run;
    }
    __syncthreads();
    *total_out = tot;
    return sv + wo[w];
}

// ---------------- kernels --------------------------------------------------

// fused: ea partial sums | W2->bf16 | degree count | u/aev precompute (warp-per-output)
__global__ void k_init(const float* __restrict__ ea,  const float* __restrict__ W2,
                       const int*   __restrict__ ei,
                       const float* __restrict__ W1,  const float* __restrict__ We1,
                       const float* __restrict__ We2,
                       const float* __restrict__ as1, const float* __restrict__ ad1,
                       const float* __restrict__ ae1,
                       const float* __restrict__ as2, const float* __restrict__ ad2,
                       const float* __restrict__ ae2) {
    int b = blockIdx.x, t = threadIdx.x;
    if (b < IB_EAP) {
        __shared__ float sm[256 * EDD];
        float loc[EDD];
#pragma unroll
        for (int d = 0; d < EDD; d++) loc[d] = 0.f;
        int r0 = b * EAP_ROWS;
        for (int r = t; r < EAP_ROWS; r += 256) {
            const float* p = ea + (size_t)(r0 + r) * EDD;
#pragma unroll
            for (int d = 0; d < EDD; d++) loc[d] += p[d];
        }
#pragma unroll
        for (int d = 0; d < EDD; d++) sm[t * EDD + d] = loc[d];
        __syncthreads();
        for (int off = 128; off > 0; off >>= 1) {
            if (t < off) {
#pragma unroll
                for (int d = 0; d < EDD; d++) sm[t * EDD + d] += sm[(t + off) * EDD + d];
            }
            __syncthreads();
        }
        if (t < EDD) g_eapart[b * EDD + t] = sm[t];
    } else if (b < IB_EAP + IB_W2) {
        int idx = (b - IB_EAP) * 256 + t;
        g_W2b[idx] = __float2bfloat16(W2[idx]);
    } else if (b < IB_EAP + IB_W2 + IB_CNT) {
        int e = (b - IB_EAP - IB_W2) * 256 + t;
        if (e < ET) {
            int d = (e < Ee) ? ei[Ee + e] : (e - Ee);
            atomicAdd(&g_deg[d], 1);
        }
    } else if (b < IB_EAP + IB_W2 + IB_CNT + IB_US2) {
        int g = (b - IB_EAP - IB_W2 - IB_CNT) * 8 + (t >> 5);   // 0..1023
        int lane = t & 31;
        if (g < 512) {
            float s = warp_dot128(W2 + (size_t)g * HIDc, as2, lane);
            if (lane == 0) g_us2[g] = s;
        } else {
            int k = g - 512;
            float s = warp_dot128(W2 + (size_t)k * HIDc, ad2, lane);
            if (lane == 0) g_ud2[k] = s;
        }
    } else {
        int g = (b - IB_EAP - IB_W2 - IB_CNT - IB_US2) * 8 + (t >> 5);  // 0..95
        int lane = t & 31;
        if (g < 44) {                       // aev1[h][d]
            int h = g / EDD, d = g % EDD;
            float s = 0.f;
#pragma unroll
            for (int c = 0; c < 4; c++)
                s = fmaf(We1[d * D1 + h * HIDc + lane + 32 * c],
                         ae1[h * HIDc + lane + 32 * c], s);
            s = warp_red(s);
            if (lane == 0) g_aev1[g] = s;
        } else if (g < 55) {                // aev2[d]
            int d = g - 44;
            float s = warp_dot128(We2 + (size_t)d * HIDc, ae2, lane);
            if (lane == 0) g_aev2[d] = s;
        } else if (g < 75) {                // us1[h*5+d]
            int o = g - 55, h = o / IND, d = o % IND;
            float s = 0.f;
#pragma unroll
            for (int c = 0; c < 4; c++)
                s = fmaf(W1[d * D1 + h * HIDc + lane + 32 * c],
                         as1[h * HIDc + lane + 32 * c], s);
            s = warp_red(s);
            if (lane == 0) g_us1[o] = s;
        } else if (g < 95) {                // ud1[h*5+d]
            int o = g - 75, h = o / IND, d = o % IND;
            float s = 0.f;
#pragma unroll
            for (int c = 0; c < 4; c++)
                s = fmaf(W1[d * D1 + h * HIDc + lane + 32 * c],
                         ad1[h * HIDc + lane + 32 * c], s);
            s = warp_red(s);
            if (lane == 0) g_ud1[o] = s;
        }
    }
}

// eamean from partials (warp per column)
__global__ void k_preE() {
    int w = threadIdx.x >> 5, lane = threadIdx.x & 31;
    if (w >= EDD) return;
    float s = 0.f;
    for (int b = lane; b < EAP_BLOCKS; b += 32) s += g_eapart[b * EDD + w];
    s = warp_red(s);
    if (lane == 0) g_eamean[w] = s / (float)Ee;
}

// single-pass decoupled-lookback scan of deg -> rowstart, cursor
__global__ void k_scan1() {
    int b = blockIdx.x, t = threadIdx.x;
    int i = b * 256 + t;
    int v = (i < Nn) ? g_deg[i] : 0;
    int tot;
    int incl = block_scan_incl(v, t, &tot);
    __shared__ int s_off;
    volatile int* flag = g_flag;
    volatile int* aggv = g_aggv;
    volatile int* inclv = g_inclv;
    if (t == 0) {
        if (b == 0) {
            inclv[0] = tot; __threadfence(); flag[0] = 2;
            s_off = 0;
        } else {
            aggv[b] = tot; __threadfence(); flag[b] = 1;
            int run = 0, j = b - 1;
            while (true) {
                int f;
                do { f = flag[j]; } while (f == 0);
                if (f == 2) { run += inclv[j]; break; }
                run += aggv[j]; j--;
            }
            inclv[b] = run + tot; __threadfence(); flag[b] = 2;
            s_off = run;
        }
    }
    __syncthreads();
    int r = s_off + incl - v;
    if (i < Nn) { g_rowstart[i] = r; g_cursor[i] = r; }
    if (b == SC_BLOCKS - 1 && t == 255) g_rowstart[Nn] = ET;
}

// attention scalars + padded x rows (8 threads per node)
__global__ void k_node1(const float* __restrict__ x) {
    int idx = blockIdx.x * blockDim.x + threadIdx.x;
    int n = idx >> 3;
    if (n >= Nn) return;
    int r = idx & 7;
    int h = r & 3;
    const float* xp = x + (size_t)n * IND;
    g_x8[(size_t)n * 8 + r] = (r < IND) ? xp[r] : 0.f;
    const float* u = (r < 4) ? (g_us1 + h * IND) : (g_ud1 + h * IND);
    float s = 0.f;
#pragma unroll
    for (int d = 0; d < IND; d++) s += xp[d] * u[d];
    if (r < 4) g_as1[n * H1c + h] = s;
    else       g_ad1[n * H1c + h] = s;
}

__global__ void k_scatter(const int* __restrict__ ei, const float* __restrict__ ea) {
    int e = blockIdx.x * blockDim.x + threadIdx.x;
    if (e >= ET) return;
    int s, d;
    float v[EDD];
    if (e < Ee) {
        s = ei[e]; d = ei[Ee + e];
        const float* p = ea + (size_t)e * EDD;
#pragma unroll
        for (int k = 0; k < EDD; k++) v[k] = p[k];
    } else {
        s = e - Ee; d = s;
#pragma unroll
        for (int k = 0; k < EDD; k++) v[k] = g_eamean[k];
    }
    int pos = atomicAdd(&g_cursor[d], 1);
    float e2 = 0.f;
#pragma unroll
    for (int k = 0; k < EDD; k++) e2 += v[k] * g_aev2[k];

    float4 asv = *(const float4*)&g_as1[s * H1c];
    float4 adv = *(const float4*)&g_ad1[d * H1c];
    float al[H1c];
#pragma unroll
    for (int h = 0; h < H1c; h++) {
        float ed = 0.f;
#pragma unroll
        for (int k = 0; k < EDD; k++) ed += v[k] * g_aev1[h * EDD + k];
        float a = ((h == 0) ? asv.x : (h == 1) ? asv.y : (h == 2) ? asv.z : asv.w)
                + ((h == 0) ? adv.x : (h == 1) ? adv.y : (h == 2) ? adv.z : adv.w) + ed;
        al[h] = (a > 0.f) ? a : NEG * a;
    }
    g_csr[(size_t)pos * 2]     = make_float4(__int_as_float(s), e2, al[0], al[1]);
    g_csr[(size_t)pos * 2 + 1] = make_float4(al[2], al[3], 0.f, 0.f);
}

// layer-1 softmax + aggregation + projection, two-phase:
//  phase 1: warp-per-node gather (input space) -> smem ax*inv
//  phase 2: block-wide projection; W1/b1/us2/ud2 in registers ONCE per block (8 nodes)
__global__ __launch_bounds__(256) void k_agg1(const float* __restrict__ W1,
                                              const float* __restrict__ b1) {
    __shared__ float s_ax[8][21];      // 20 axinv values per node, padded
    __shared__ float s_r[8][8][2];     // per-warp partials for as2/ad2
    int t = threadIdx.x;
    int w = t >> 5, lane = t & 31;
    int n0 = blockIdx.x * 8;
    int n = n0 + w;                    // Nn % 8 == 0, always valid

    // ---- phase 1 ----
    int base = g_rowstart[n];
    int deg  = g_rowstart[n + 1] - base;

    float den[H1c];
    float ax[H1c][IND];
#pragma unroll
    for (int h = 0; h < H1c; h++) {
        den[h] = 0.f;
#pragma unroll
        for (int d = 0; d < IND; d++) ax[h][d] = 0.f;
    }

    for (int i = lane; i < deg; i += 32) {
        float4 fa = g_csr[(size_t)(base + i) * 2];
        float4 fb = g_csr[(size_t)(base + i) * 2 + 1];
        int src = __float_as_int(fa.x);
        float e0 = __expf(fa.z), e1 = __expf(fa.w), e2 = __expf(fb.x), e3 = __expf(fb.y);
        den[0] += e0; den[1] += e1; den[2] += e2; den[3] += e3;
        const float* xp = g_x8 + (size_t)src * 8;
        float4 xv4 = __ldg((const float4*)xp);
        float xv5 = __ldg(xp + 4);
        float xv[IND] = {xv4.x, xv4.y, xv4.z, xv4.w, xv5};
#pragma unroll
        for (int d = 0; d < IND; d++) {
            ax[0][d] = fmaf(e0, xv[d], ax[0][d]);
            ax[1][d] = fmaf(e1, xv[d], ax[1][d]);
            ax[2][d] = fmaf(e2, xv[d], ax[2][d]);
            ax[3][d] = fmaf(e3, xv[d], ax[3][d]);
        }
    }
#pragma unroll
    for (int off = 16; off > 0; off >>= 1) {
#pragma unroll
        for (int h = 0; h < H1c; h++) {
            den[h] += __shfl_xor_sync(0xffffffffu, den[h], off);
#pragma unroll
            for (int d = 0; d < IND; d++)
                ax[h][d] += __shfl_xor_sync(0xffffffffu, ax[h][d], off);
        }
    }
    if (lane < 20) {
        int h = lane / IND, d = lane % IND;
        s_ax[w][lane] = ax[h][d] * (1.f / (den[h] + 1e-16f));
    }
    __syncthreads();

    // ---- phase 2 ----
    int c0 = t * 2;
    int h2 = c0 >> 7;
    float2 wv[IND];
#pragma unroll
    for (int d = 0; d < IND; d++) wv[d] = *(const float2*)&W1[d * D1 + c0];
    float2 bb = *(const float2*)&b1[c0];
    float2 u  = *(const float2*)&g_us2[c0];
    float2 ud = *(const float2*)&g_ud2[c0];

    float pS[8], pD[8];
#pragma unroll
    for (int q = 0; q < 8; q++) {
        float a0 = bb.x, a1 = bb.y;
#pragma unroll
        for (int d = 0; d < IND; d++) {
            float av = s_ax[q][h2 * IND + d];
            a0 = fmaf(av, wv[d].x, a0);
            a1 = fmaf(av, wv[d].y, a1);
        }
        a0 = (a0 > 0.f) ? a0 : 0.f;
        a1 = (a1 > 0.f) ? a1 : 0.f;
        *(__nv_bfloat162*)(g_h1b + (size_t)(n0 + q) * D1 + c0) =
            __float22bfloat162_rn(make_float2(a0, a1));
        pS[q] = fmaf(a0, u.x,  a1 * u.y);
        pD[q] = fmaf(a0, ud.x, a1 * ud.y);
    }
#pragma unroll
    for (int q = 0; q < 8; q++) {
        pS[q] = warp_red(pS[q]);
        pD[q] = warp_red(pD[q]);
    }
    if (lane == 0) {
#pragma unroll
        for (int q = 0; q < 8; q++) {
            s_r[q][w][0] = pS[q];
            s_r[q][w][1] = pD[q];
        }
    }
    __syncthreads();
    if (t < 16) {
        int q = t >> 1, which = t & 1;
        float s = 0.f;
#pragma unroll
        for (int ww = 0; ww < 8; ww++) s += s_r[q][ww][which];
        if (which == 0) g_as2[n0 + q] = s;
        else            g_ad2[n0 + q] = s;
    }
}

// xh2 = h1 @ W2 : bf16 wmma (HMMA), 128x128 CTA tile, K chunks of 64,
// cp.async double-buffered; bf16x2 packed output staged through smem.
#define KC 64
#define A_ELEMS 9216    /* 128 * 72 */
#define B_ELEMS 8704    /* 64 * 136 */
#define A_BYTES 18432
#define B_BYTES 17408
#define GSM_TOTAL (2 * (A_BYTES + B_BYTES))   /* 71680 >= 65536 for C staging */

__global__ __launch_bounds__(256, 2) void k_gemm() {
    extern __shared__ char smc[];
    __nv_bfloat16* As = (__nv_bfloat16*)smc;                     // [2][128][72]
    __nv_bfloat16* Bs = (__nv_bfloat16*)(smc + 2 * A_BYTES);     // [2][64][136]
    uint32_t smA = smem_u32(As);
    uint32_t smB = smem_u32(Bs);

    int t = threadIdx.x;
    int wid = t >> 5;
    int row0 = blockIdx.x * 128;
    int wm0 = (wid >> 2) * 64;     // 0 or 64
    int wn0 = (wid & 3) * 32;      // 0,32,64,96

    wmma::fragment<wmma::accumulator, 16, 16, 16, float> acc[4][2];
#pragma unroll
    for (int m = 0; m < 4; m++)
#pragma unroll
        for (int n = 0; n < 2; n++) wmma::fill_fragment(acc[m][n], 0.f);

    auto load_chunk = [&](int buf, int k0) {
#pragma unroll
        for (int i = 0; i < 4; i++) {
            int v = i * 256 + t;
            int r = v >> 3, c8 = v & 7;                 // A: 128 rows x 8 uint4
            cp_async16(smA + (uint32_t)(buf * A_ELEMS + r * 72 + c8 * 8) * 2,
                       g_h1b + (size_t)(row0 + r) * D1 + k0 + c8 * 8);
        }
#pragma unroll
        for (int i = 0; i < 4; i++) {
            int v = i * 256 + t;
            int r = v >> 4, c8 = v & 15;                // B: 64 rows x 16 uint4
            cp_async16(smB + (uint32_t)(buf * B_ELEMS + r * 136 + c8 * 8) * 2,
                       g_W2b + (size_t)(k0 + r) * HIDc + c8 * 8);
        }
        CP_COMMIT();
    };

    load_chunk(0, 0);
    int buf = 0;
#pragma unroll
    for (int c = 0; c < 8; c++) {
        if (c < 7) load_chunk(buf ^ 1, (c + 1) * KC);
        if (c < 7) CP_WAIT1(); else CP_WAIT0();
        __syncthreads();

        const __nv_bfloat16* Ab = As + buf * A_ELEMS;
        const __nv_bfloat16* Bb = Bs + buf * B_ELEMS;
#pragma unroll
        for (int kk = 0; kk < 4; kk++) {
            wmma::fragment<wmma::matrix_a, 16, 16, 16, __nv_bfloat16, wmma::row_major> af[4];
            wmma::fragment<wmma::matrix_b, 16, 16, 16, __nv_bfloat16, wmma::row_major> bf[2];
#pragma unroll
            for (int m = 0; m < 4; m++)
                wmma::load_matrix_sync(af[m], Ab + (wm0 + m * 16) * 72 + kk * 16, 72);
#pragma unroll
            for (int n = 0; n < 2; n++)
                wmma::load_matrix_sync(bf[n], Bb + (kk * 16) * 136 + wn0 + n * 16, 136);
#pragma unroll
            for (int m = 0; m < 4; m++)
#pragma unroll
                for (int n = 0; n < 2; n++)
                    wmma::mma_sync(acc[m][n], af[m], bf[n], acc[m][n]);
        }
        __syncthreads();
        buf ^= 1;
    }

    // stage fp32 C in smem, emit packed bf16x2
    float* Cs = (float*)smc;    // 128*128 fp32 = 64KB
#pragma unroll
    for (int m = 0; m < 4; m++)
#pragma unroll
        for (int n = 0; n < 2; n++)
            wmma::store_matrix_sync(Cs + (size_t)(wm0 + m * 16) * 128 + wn0 + n * 16,
                                    acc[m][n], 128, wmma::mem_row_major);
    __syncthreads();
#pragma unroll
    for (int j = 0; j < 32; j++) {
        int idx = j * 256 + t;          // 8192 bf16x2 pairs
        int row = idx >> 6, cp = idx & 63;
        float2 f = *(const float2*)&Cs[row * 128 + cp * 2];
        __nv_bfloat162 bv = __float22bfloat162_rn(f);
        g_xh2b[(size_t)(row0 + row) * 64 + cp] = *(uint32_t*)&bv;
    }
}

// layer-2 softmax + aggregation + final linear + sigmoid, fused per dst.
__global__ __launch_bounds__(128) void k_agg2(const float* __restrict__ b2,
                                              const float* __restrict__ Wfc,
                                              const float* __restrict__ bfc,
                                              float* __restrict__ out) {
    int n = blockIdx.x, t = threadIdx.x;
    int base = g_rowstart[n];
    int deg  = g_rowstart[n + 1] - base;
    __shared__ float s_ex[CAP2];
    __shared__ int   s_src[CAP2];
    __shared__ float s_w[4];
    __shared__ float s_den;
    __shared__ float2 s_half[2][64];
    __shared__ float s_red[2];

    float ad = g_ad2[n];
    float partial = 0.f;
    for (int i = t; i < deg; i += 128) {
        float4 f = g_csr[(size_t)(base + i) * 2];
        int src = __float_as_int(f.x);
        float al = g_as2[src] + ad + f.y;
        al = (al > 0.f) ? al : NEG * al;
        float ex = __expf(al);
        partial += ex;
        if (i < CAP2) { s_ex[i] = ex; s_src[i] = src; }
    }
    for (int off = 16; off > 0; off >>= 1)
        partial += __shfl_down_sync(0xffffffffu, partial, off);
    if ((t & 31) == 0) s_w[t >> 5] = partial;
    __syncthreads();
    if (t == 0) s_den = s_w[0] + s_w[1] + s_w[2] + s_w[3];
    __syncthreads();
    float inv = 1.f / (s_den + 1e-16f);

    int eh = t >> 6, p = t & 63;
    float2 a0 = {0.f, 0.f}, a1 = {0.f, 0.f}, a2 = {0.f, 0.f}, a3 = {0.f, 0.f};

    auto step = [&](int i, float2& a) {
        float ex; int src;
        if (i < CAP2) { ex = s_ex[i]; src = s_src[i]; }
        else {
            float4 f = g_csr[(size_t)(base + i) * 2];
            src = __float_as_int(f.x);
            float al = g_as2[src] + ad + f.y;
            al = (al > 0.f) ? al : NEG * al;
            ex = __expf(al);
        }
        uint32_t raw = g_xh2b[(size_t)src * 64 + p];
        __nv_bfloat162 bv = *(__nv_bfloat162*)&raw;
        float2 fv = __bfloat1622float2(bv);
        a.x = fmaf(ex, fv.x, a.x);
        a.y = fmaf(ex, fv.y, a.y);
    };

    int i = eh;
    for (; i + 6 < deg; i += 8) {
        step(i, a0); step(i + 2, a1); step(i + 4, a2); step(i + 6, a3);
    }
    for (; i < deg; i += 2) step(i, a0);
    a0.x = (a0.x + a1.x) + (a2.x + a3.x);
    a0.y = (a0.y + a1.y) + (a2.y + a3.y);

    s_half[eh][p] = a0;
    __syncthreads();

    if (t < 64) {
        float2 hA = s_half[0][t], hB = s_half[1][t];
        float h0 = (hA.x + hB.x) * inv;
        float h1 = (hA.y + hB.y) * inv;
        float2 bb = *(const float2*)&b2[2 * t];
        h0 += bb.x; h1 += bb.y;
        h0 = (h0 > 0.f) ? h0 : 0.f;
        h1 = (h1 > 0.f) ? h1 : 0.f;
        float2 wf = *(const float2*)&Wfc[2 * t];
        float part = fmaf(h0, wf.x, h1 * wf.y);
        for (int off = 16; off > 0; off >>= 1)
            part += __shfl_down_sync(0xffffffffu, part, off);
        if ((t & 31) == 0) s_red[t >> 5] = part;
    }
    __syncthreads();
    if (t == 0) {
        float z = s_red[0] + s_red[1] + bfc[0];
        out[n] = 1.f / (1.f + __expf(-z));
    }
}

// ---------------- launcher -------------------------------------------------

extern "C" void kernel_launch(void* const* d_in, const int* in_sizes, int n_in,
                              void* d_out, int out_size) {
    const float* x    = (const float*)d_in[0];
    const int*   ei   = (const int*)  d_in[1];
    const float* ea   = (const float*)d_in[2];
    const float* W1   = (const float*)d_in[3];
    const float* We1  = (const float*)d_in[4];
    const float* as1v = (const float*)d_in[5];
    const float* ad1v = (const float*)d_in[6];
    const float* ae1v = (const float*)d_in[7];
    const float* b1   = (const float*)d_in[8];
    const float* W2   = (const float*)d_in[9];
    const float* We2  = (const float*)d_in[10];
    const float* as2v = (const float*)d_in[11];
    const float* ad2v = (const float*)d_in[12];
    const float* ae2v = (const float*)d_in[13];
    const float* b2   = (const float*)d_in[14];
    const float* Wfc  = (const float*)d_in[15];
    const float* bfc  = (const float*)d_in[16];
    float* out = (float*)d_out;

    static void* p_deg = nullptr;
    static void* p_flag = nullptr;
    if (!p_deg) {
        cudaFuncSetAttribute(k_gemm, cudaFuncAttributeMaxDynamicSharedMemorySize, GSM_TOTAL);
        cudaGetSymbolAddress(&p_deg, g_deg);
        cudaGetSymbolAddress(&p_flag, g_flag);
    }

    cudaMemsetAsync(p_deg, 0, Nn * sizeof(int));
    cudaMemsetAsync(p_flag, 0, SC_BLOCKS * sizeof(int));
    k_init<<<IB_TOTAL, 256>>>(ea, W2, ei, W1, We1, We2,
                              as1v, ad1v, ae1v, as2v, ad2v, ae2v);
    k_preE<<<1, 384>>>();
    k_scan1<<<SC_BLOCKS, 256>>>();
    k_node1<<<(Nn * 8 + 255) / 256, 256>>>(x);
    k_scatter<<<(ET + 255) / 256, 256>>>(ei, ea);
    k_agg1<<<Nn / 8, 256>>>(W1, b1);
    k_gemm<<<MROWS / 128, 256, GSM_TOTAL>>>();
    k_agg2<<<Nn, 128>>>(b2, Wfc, bfc, out);
}

// round 12
// speedup vs baseline: 1.1789x; 1.0563x over previous
#include <cuda_runtime.h>
#include <cuda_bf16.h>
#include <mma.h>
#include <cstdint>

using namespace nvcuda;

#define Nn 40000
#define Ee 640000
#define ET 680000   /* Ee + Nn self loops */
#define HIDc 128
#define H1c 4
#define D1 512      /* H1*HID */
#define IND 5
#define EDD 11
#define NEG 0.2f

#define EAP_BLOCKS 640
#define EAP_ROWS 1000
#define CAP2 96

#define MROWS 40064          /* 313 * 128, padded M */
#define SC_BLOCKS 157        /* ceil(40000/256) scan blocks */

/* k_init block ranges */
#define IB_EAP  640
#define IB_W2   256
#define IB_CNT  2657         /* ceil(680000/256) */
#define IB_US2  128          /* 1024 warp-outputs: us2/ud2 */
#define IB_MISC 12           /* 95 warp-outputs: aev1,aev2,us1,ud1 */
#define IB_TOTAL (IB_EAP + IB_W2 + IB_CNT + IB_US2 + IB_MISC)

// ---------------- scratch (device globals; no allocation allowed) ----------
__device__ __nv_bfloat16 g_h1b[(size_t)MROWS * D1];     // padded rows stay zero
__device__ uint32_t g_xh2b[(size_t)MROWS * 64];         // bf16x2 packed
__device__ __nv_bfloat16 g_W2b[D1 * HIDc];
__device__ float g_x8[(size_t)Nn * 8];                  // padded x rows (32B)
__device__ float g_as1[Nn * H1c];
__device__ float g_ad1[Nn * H1c];
__device__ float g_as2[Nn];
__device__ float g_ad2[Nn];
__device__ int   g_deg[Nn];
__device__ int   g_rowstart[Nn + 1];
__device__ int   g_cursor[Nn];
__device__ int   g_flag[SC_BLOCKS];
__device__ int   g_aggv[SC_BLOCKS];
__device__ int   g_inclv[SC_BLOCKS];
__device__ float4 g_csr[(size_t)ET * 2];   // AoS: {src,e2,a1_0,a1_1},{a1_2,a1_3,-,-}
__device__ float g_eamean[EDD];
__device__ float g_eapart[EAP_BLOCKS * EDD];
__device__ float g_aev1[H1c * EDD];
__device__ float g_aev2[EDD];
__device__ float g_us1[H1c * IND];
__device__ float g_ud1[H1c * IND];
__device__ float g_us2[D1];
__device__ float g_ud2[D1];

// ---------------- small helpers --------------------------------------------
__device__ __forceinline__ uint32_t smem_u32(const void* p) {
    uint32_t a;
    asm("{ .reg .u64 t; cvta.to.shared.u64 t, %1; cvt.u32.u64 %0, t; }" : "=r"(a) : "l"(p));
    return a;
}
__device__ __forceinline__ void cp_async16(uint32_t dst, const void* src) {
    asm volatile("cp.async.cg.shared.global [%0], [%1], 16;" :: "r"(dst), "l"(src));
}
#define CP_COMMIT() asm volatile("cp.async.commit_group;" ::: "memory")
#define CP_WAIT1()  asm volatile("cp.async.wait_group 1;" ::: "memory")
#define CP_WAIT0()  asm volatile("cp.async.wait_group 0;" ::: "memory")

__device__ __forceinline__ float warp_red(float v) {
#pragma unroll
    for (int off = 16; off > 0; off >>= 1)
        v += __shfl_down_sync(0xffffffffu, v, off);
    return v;
}

__device__ __forceinline__ float warp_dot128(const float* a, const float* b, int lane) {
    float s = 0.f;
#pragma unroll
    for (int c = 0; c < 4; c++) s = fmaf(a[lane + 32 * c], b[lane + 32 * c], s);
    return warp_red(s);
}

// block-wide inclusive scan helper (256 threads)
__device__ __forceinline__ int block_scan_incl(int v, int t, int* total_out) {
    int lane = t & 31, w = t >> 5;
    int sv = v;
#pragma unroll
    for (int off = 1; off < 32; off <<= 1) {
        int nv = __shfl_up_sync(0xffffffffu, sv, off);
        if (lane >= off) sv += nv;
    }
    __shared__ int ws[8];
    __shared__ int wo[8];
    __shared__ int tot;
    if (lane == 31) ws[w] = sv;
    __syncthreads();
    if (t == 0) {
        int run = 0;
#pragma unroll
        for (int k = 0; k < 8; k++) { wo[k] = run; run += ws[k]; }
        tot = run;
    }
    __syncthreads();
    *total_out = tot;
    return sv + wo[w];
}

// ---------------- kernels --------------------------------------------------

// fused: ea partial sums | W2->bf16 | degree count | u/aev precompute (warp-per-output)
__global__ void k_init(const float* __restrict__ ea,  const float* __restrict__ W2,
                       const int*   __restrict__ ei,
                       const float* __restrict__ W1,  const float* __restrict__ We1,
                       const float* __restrict__ We2,
                       const float* __restrict__ as1, const float* __restrict__ ad1,
                       const float* __restrict__ ae1,
                       const float* __restrict__ as2, const float* __restrict__ ad2,
                       const float* __restrict__ ae2) {
    int b = blockIdx.x, t = threadIdx.x;
    if (b < IB_EAP) {
        __shared__ float sm[256 * EDD];
        float loc[EDD];
#pragma unroll
        for (int d = 0; d < EDD; d++) loc[d] = 0.f;
        int r0 = b * EAP_ROWS;
        for (int r = t; r < EAP_ROWS; r += 256) {
            const float* p = ea + (size_t)(r0 + r) * EDD;
#pragma unroll
            for (int d = 0; d < EDD; d++) loc[d] += p[d];
        }
#pragma unroll
        for (int d = 0; d < EDD; d++) sm[t * EDD + d] = loc[d];
        __syncthreads();
        for (int off = 128; off > 0; off >>= 1) {
            if (t < off) {
#pragma unroll
                for (int d = 0; d < EDD; d++) sm[t * EDD + d] += sm[(t + off) * EDD + d];
            }
            __syncthreads();
        }
        if (t < EDD) g_eapart[b * EDD + t] = sm[t];
    } else if (b < IB_EAP + IB_W2) {
        int idx = (b - IB_EAP) * 256 + t;
        g_W2b[idx] = __float2bfloat16(W2[idx]);
    } else if (b < IB_EAP + IB_W2 + IB_CNT) {
        int e = (b - IB_EAP - IB_W2) * 256 + t;
        if (e < ET) {
            int d = (e < Ee) ? ei[Ee + e] : (e - Ee);
            atomicAdd(&g_deg[d], 1);
        }
    } else if (b < IB_EAP + IB_W2 + IB_CNT + IB_US2) {
        int g = (b - IB_EAP - IB_W2 - IB_CNT) * 8 + (t >> 5);   // 0..1023
        int lane = t & 31;
        if (g < 512) {
            float s = warp_dot128(W2 + (size_t)g * HIDc, as2, lane);
            if (lane == 0) g_us2[g] = s;
        } else {
            int k = g - 512;
            float s = warp_dot128(W2 + (size_t)k * HIDc, ad2, lane);
            if (lane == 0) g_ud2[k] = s;
        }
    } else {
        int g = (b - IB_EAP - IB_W2 - IB_CNT - IB_US2) * 8 + (t >> 5);  // 0..95
        int lane = t & 31;
        if (g < 44) {                       // aev1[h][d]
            int h = g / EDD, d = g % EDD;
            float s = 0.f;
#pragma unroll
            for (int c = 0; c < 4; c++)
                s = fmaf(We1[d * D1 + h * HIDc + lane + 32 * c],
                         ae1[h * HIDc + lane + 32 * c], s);
            s = warp_red(s);
            if (lane == 0) g_aev1[g] = s;
        } else if (g < 55) {                // aev2[d]
            int d = g - 44;
            float s = warp_dot128(We2 + (size_t)d * HIDc, ae2, lane);
            if (lane == 0) g_aev2[d] = s;
        } else if (g < 75) {                // us1[h*5+d]
            int o = g - 55, h = o / IND, d = o % IND;
            float s = 0.f;
#pragma unroll
            for (int c = 0; c < 4; c++)
                s = fmaf(W1[d * D1 + h * HIDc + lane + 32 * c],
                         as1[h * HIDc + lane + 32 * c], s);
            s = warp_red(s);
            if (lane == 0) g_us1[o] = s;
        } else if (g < 95) {                // ud1[h*5+d]
            int o = g - 75, h = o / IND, d = o % IND;
            float s = 0.f;
#pragma unroll
            for (int c = 0; c < 4; c++)
                s = fmaf(W1[d * D1 + h * HIDc + lane + 32 * c],
                         ad1[h * HIDc + lane + 32 * c], s);
            s = warp_red(s);
            if (lane == 0) g_ud1[o] = s;
        }
    }
}

// eamean from partials (warp per column)
__global__ void k_preE() {
    int w = threadIdx.x >> 5, lane = threadIdx.x & 31;
    if (w >= EDD) return;
    float s = 0.f;
    for (int b = lane; b < EAP_BLOCKS; b += 32) s += g_eapart[b * EDD + w];
    s = warp_red(s);
    if (lane == 0) g_eamean[w] = s / (float)Ee;
}

// single-pass decoupled-lookback scan of deg -> rowstart, cursor
__global__ void k_scan1() {
    int b = blockIdx.x, t = threadIdx.x;
    int i = b * 256 + t;
    int v = (i < Nn) ? g_deg[i] : 0;
    int tot;
    int incl = block_scan_incl(v, t, &tot);
    __shared__ int s_off;
    volatile int* flag = g_flag;
    volatile int* aggv = g_aggv;
    volatile int* inclv = g_inclv;
    if (t == 0) {
        if (b == 0) {
            inclv[0] = tot; __threadfence(); flag[0] = 2;
            s_off = 0;
        } else {
            aggv[b] = tot; __threadfence(); flag[b] = 1;
            int run = 0, j = b - 1;
            while (true) {
                int f;
                do { f = flag[j]; } while (f == 0);
                if (f == 2) { run += inclv[j]; break; }
                run += aggv[j]; j--;
            }
            inclv[b] = run + tot; __threadfence(); flag[b] = 2;
            s_off = run;
        }
    }
    __syncthreads();
    int r = s_off + incl - v;
    if (i < Nn) { g_rowstart[i] = r; g_cursor[i] = r; }
    if (b == SC_BLOCKS - 1 && t == 255) g_rowstart[Nn] = ET;
}

// attention scalars + padded x rows (8 threads per node)
__global__ void k_node1(const float* __restrict__ x) {
    int idx = blockIdx.x * blockDim.x + threadIdx.x;
    int n = idx >> 3;
    if (n >= Nn) return;
    int r = idx & 7;
    int h = r & 3;
    const float* xp = x + (size_t)n * IND;
    g_x8[(size_t)n * 8 + r] = (r < IND) ? xp[r] : 0.f;
    const float* u = (r < 4) ? (g_us1 + h * IND) : (g_ud1 + h * IND);
    float s = 0.f;
#pragma unroll
    for (int d = 0; d < IND; d++) s += xp[d] * u[d];
    if (r < 4) g_as1[n * H1c + h] = s;
    else       g_ad1[n * H1c + h] = s;
}

__global__ void k_scatter(const int* __restrict__ ei, const float* __restrict__ ea) {
    int e = blockIdx.x * blockDim.x + threadIdx.x;
    if (e >= ET) return;
    int s, d;
    float v[EDD];
    if (e < Ee) {
        s = ei[e]; d = ei[Ee + e];
        const float* p = ea + (size_t)e * EDD;
#pragma unroll
        for (int k = 0; k < EDD; k++) v[k] = p[k];
    } else {
        s = e - Ee; d = s;
#pragma unroll
        for (int k = 0; k < EDD; k++) v[k] = g_eamean[k];
    }
    int pos = atomicAdd(&g_cursor[d], 1);
    float e2 = 0.f;
#pragma unroll
    for (int k = 0; k < EDD; k++) e2 += v[k] * g_aev2[k];

    float4 asv = *(const float4*)&g_as1[s * H1c];
    float4 adv = *(const float4*)&g_ad1[d * H1c];
    float al[H1c];
#pragma unroll
    for (int h = 0; h < H1c; h++) {
        float ed = 0.f;
#pragma unroll
        for (int k = 0; k < EDD; k++) ed += v[k] * g_aev1[h * EDD + k];
        float a = ((h == 0) ? asv.x : (h == 1) ? asv.y : (h == 2) ? asv.z : asv.w)
                + ((h == 0) ? adv.x : (h == 1) ? adv.y : (h == 2) ? adv.z : adv.w) + ed;
        al[h] = (a > 0.f) ? a : NEG * a;
    }
    g_csr[(size_t)pos * 2]     = make_float4(__int_as_float(s), e2, al[0], al[1]);
    g_csr[(size_t)pos * 2 + 1] = make_float4(al[2], al[3], 0.f, 0.f);
}

// layer-1 softmax + aggregation + projection, three-phase:
//  phase 1: warp-per-node gather (input space) + butterfly -> smem ax*inv
//  phase 2: thread-per-channel-pair projection, W1/b1 in regs once per block;
//           h1 bf16x2 to global AND smem
//  phase 3: warp-per-node as2/ad2 reduction from smem h1 (2 warp_reds, = R8 count)
__global__ __launch_bounds__(256) void k_agg1(const float* __restrict__ W1,
                                              const float* __restrict__ b1) {
    __shared__ float s_ax[8][21];
    __shared__ uint32_t s_h1[8][256];       // bf16x2 packed, 8 KB
    __shared__ float s_u[D1];
    __shared__ float s_ud[D1];
    int t = threadIdx.x;
    int w = t >> 5, lane = t & 31;
    int n0 = blockIdx.x * 8;
    int n = n0 + w;                         // Nn % 8 == 0

    // stage us2/ud2 coalesced (independent of phase 1)
#pragma unroll
    for (int i = 0; i < 2; i++) {
        s_u [t + i * 256] = g_us2[t + i * 256];
        s_ud[t + i * 256] = g_ud2[t + i * 256];
    }

    // ---- phase 1: gather ----
    int base = g_rowstart[n];
    int deg  = g_rowstart[n + 1] - base;

    float den[H1c];
    float ax[H1c][IND];
#pragma unroll
    for (int h = 0; h < H1c; h++) {
        den[h] = 0.f;
#pragma unroll
        for (int d = 0; d < IND; d++) ax[h][d] = 0.f;
    }

    for (int i = lane; i < deg; i += 32) {
        float4 fa = g_csr[(size_t)(base + i) * 2];
        float4 fb = g_csr[(size_t)(base + i) * 2 + 1];
        int src = __float_as_int(fa.x);
        float e0 = __expf(fa.z), e1 = __expf(fa.w), e2 = __expf(fb.x), e3 = __expf(fb.y);
        den[0] += e0; den[1] += e1; den[2] += e2; den[3] += e3;
        const float* xp = g_x8 + (size_t)src * 8;
        float4 xv4 = __ldg((const float4*)xp);
        float xv5 = __ldg(xp + 4);
        float xv[IND] = {xv4.x, xv4.y, xv4.z, xv4.w, xv5};
#pragma unroll
        for (int d = 0; d < IND; d++) {
            ax[0][d] = fmaf(e0, xv[d], ax[0][d]);
            ax[1][d] = fmaf(e1, xv[d], ax[1][d]);
            ax[2][d] = fmaf(e2, xv[d], ax[2][d]);
            ax[3][d] = fmaf(e3, xv[d], ax[3][d]);
        }
    }
#pragma unroll
    for (int off = 16; off > 0; off >>= 1) {
#pragma unroll
        for (int h = 0; h < H1c; h++) {
            den[h] += __shfl_xor_sync(0xffffffffu, den[h], off);
#pragma unroll
            for (int d = 0; d < IND; d++)
                ax[h][d] += __shfl_xor_sync(0xffffffffu, ax[h][d], off);
        }
    }
    if (lane < 20) {
        int h = lane / IND, d = lane % IND;
        s_ax[w][lane] = ax[h][d] * (1.f / (den[h] + 1e-16f));
    }
    __syncthreads();

    // ---- phase 2: projection, W1/b1 in regs once per block ----
    int c0 = t * 2;
    int h2 = c0 >> 7;
    float2 wv[IND];
#pragma unroll
    for (int d = 0; d < IND; d++) wv[d] = *(const float2*)&W1[d * D1 + c0];
    float2 bb = *(const float2*)&b1[c0];

#pragma unroll
    for (int q = 0; q < 8; q++) {
        float a0 = bb.x, a1 = bb.y;
#pragma unroll
        for (int d = 0; d < IND; d++) {
            float av = s_ax[q][h2 * IND + d];
            a0 = fmaf(av, wv[d].x, a0);
            a1 = fmaf(av, wv[d].y, a1);
        }
        a0 = (a0 > 0.f) ? a0 : 0.f;
        a1 = (a1 > 0.f) ? a1 : 0.f;
        __nv_bfloat162 bv = __float22bfloat162_rn(make_float2(a0, a1));
        *(__nv_bfloat162*)(g_h1b + (size_t)(n0 + q) * D1 + c0) = bv;
        s_h1[q][t] = *(uint32_t*)&bv;
    }
    __syncthreads();

    // ---- phase 3: warp w reduces node w's as2/ad2 from smem h1 ----
    float s2 = 0.f, d2v = 0.f;
#pragma unroll
    for (int j = 0; j < 8; j++) {
        int c = j * 32 + lane;
        uint32_t raw = s_h1[w][c];
        float2 f = __bfloat1622float2(*(__nv_bfloat162*)&raw);
        s2  = fmaf(f.x, s_u [2 * c], fmaf(f.y, s_u [2 * c + 1], s2));
        d2v = fmaf(f.x, s_ud[2 * c], fmaf(f.y, s_ud[2 * c + 1], d2v));
    }
    s2  = warp_red(s2);
    d2v = warp_red(d2v);
    if (lane == 0) { g_as2[n] = s2; g_ad2[n] = d2v; }
}

// xh2 = h1 @ W2 : bf16 wmma (HMMA), 128x128 CTA tile, K chunks of 64,
// cp.async double-buffered; bf16x2 packed output staged through smem.
#define KC 64
#define A_ELEMS 9216    /* 128 * 72 */
#define B_ELEMS 8704    /* 64 * 136 */
#define A_BYTES 18432
#define B_BYTES 17408
#define GSM_TOTAL (2 * (A_BYTES + B_BYTES))   /* 71680 >= 65536 for C staging */

__global__ __launch_bounds__(256, 2) void k_gemm() {
    extern __shared__ char smc[];
    __nv_bfloat16* As = (__nv_bfloat16*)smc;                     // [2][128][72]
    __nv_bfloat16* Bs = (__nv_bfloat16*)(smc + 2 * A_BYTES);     // [2][64][136]
    uint32_t smA = smem_u32(As);
    uint32_t smB = smem_u32(Bs);

    int t = threadIdx.x;
    int wid = t >> 5;
    int row0 = blockIdx.x * 128;
    int wm0 = (wid >> 2) * 64;     // 0 or 64
    int wn0 = (wid & 3) * 32;      // 0,32,64,96

    wmma::fragment<wmma::accumulator, 16, 16, 16, float> acc[4][2];
#pragma unroll
    for (int m = 0; m < 4; m++)
#pragma unroll
        for (int n = 0; n < 2; n++) wmma::fill_fragment(acc[m][n], 0.f);

    auto load_chunk = [&](int buf, int k0) {
#pragma unroll
        for (int i = 0; i < 4; i++) {
            int v = i * 256 + t;
            int r = v >> 3, c8 = v & 7;                 // A: 128 rows x 8 uint4
            cp_async16(smA + (uint32_t)(buf * A_ELEMS + r * 72 + c8 * 8) * 2,
                       g_h1b + (size_t)(row0 + r) * D1 + k0 + c8 * 8);
        }
#pragma unroll
        for (int i = 0; i < 4; i++) {
            int v = i * 256 + t;
            int r = v >> 4, c8 = v & 15;                // B: 64 rows x 16 uint4
            cp_async16(smB + (uint32_t)(buf * B_ELEMS + r * 136 + c8 * 8) * 2,
                       g_W2b + (size_t)(k0 + r) * HIDc + c8 * 8);
        }
        CP_COMMIT();
    };

    load_chunk(0, 0);
    int buf = 0;
#pragma unroll
    for (int c = 0; c < 8; c++) {
        if (c < 7) load_chunk(buf ^ 1, (c + 1) * KC);
        if (c < 7) CP_WAIT1(); else CP_WAIT0();
        __syncthreads();

        const __nv_bfloat16* Ab = As + buf * A_ELEMS;
        const __nv_bfloat16* Bb = Bs + buf * B_ELEMS;
#pragma unroll
        for (int kk = 0; kk < 4; kk++) {
            wmma::fragment<wmma::matrix_a, 16, 16, 16, __nv_bfloat16, wmma::row_major> af[4];
            wmma::fragment<wmma::matrix_b, 16, 16, 16, __nv_bfloat16, wmma::row_major> bf[2];
#pragma unroll
            for (int m = 0; m < 4; m++)
                wmma::load_matrix_sync(af[m], Ab + (wm0 + m * 16) * 72 + kk * 16, 72);
#pragma unroll
            for (int n = 0; n < 2; n++)
                wmma::load_matrix_sync(bf[n], Bb + (kk * 16) * 136 + wn0 + n * 16, 136);
#pragma unroll
            for (int m = 0; m < 4; m++)
#pragma unroll
                for (int n = 0; n < 2; n++)
                    wmma::mma_sync(acc[m][n], af[m], bf[n], acc[m][n]);
        }
        __syncthreads();
        buf ^= 1;
    }

    // stage fp32 C in smem, emit packed bf16x2
    float* Cs = (float*)smc;    // 128*128 fp32 = 64KB
#pragma unroll
    for (int m = 0; m < 4; m++)
#pragma unroll
        for (int n = 0; n < 2; n++)
            wmma::store_matrix_sync(Cs + (size_t)(wm0 + m * 16) * 128 + wn0 + n * 16,
                                    acc[m][n], 128, wmma::mem_row_major);
    __syncthreads();
#pragma unroll
    for (int j = 0; j < 32; j++) {
        int idx = j * 256 + t;          // 8192 bf16x2 pairs
        int row = idx >> 6, cp = idx & 63;
        float2 f = *(const float2*)&Cs[row * 128 + cp * 2];
        __nv_bfloat162 bv = __float22bfloat162_rn(f);
        g_xh2b[(size_t)(row0 + row) * 64 + cp] = *(uint32_t*)&bv;
    }
}

// layer-2 softmax + aggregation + final linear + sigmoid, fused per dst.
__global__ __launch_bounds__(128) void k_agg2(const float* __restrict__ b2,
                                              const float* __restrict__ Wfc,
                                              const float* __restrict__ bfc,
                                              float* __restrict__ out) {
    int n = blockIdx.x, t = threadIdx.x;
    int base = g_rowstart[n];
    int deg  = g_rowstart[n + 1] - base;
    __shared__ float s_ex[CAP2];
    __shared__ int   s_src[CAP2];
    __shared__ float s_w[4];
    __shared__ float s_den;
    __shared__ float2 s_half[2][64];
    __shared__ float s_red[2];

    float ad = g_ad2[n];
    float partial = 0.f;
    for (int i = t; i < deg; i += 128) {
        float4 f = g_csr[(size_t)(base + i) * 2];
        int src = __float_as_int(f.x);
        float al = g_as2[src] + ad + f.y;
        al = (al > 0.f) ? al : NEG * al;
        float ex = __expf(al);
        partial += ex;
        if (i < CAP2) { s_ex[i] = ex; s_src[i] = src; }
    }
    for (int off = 16; off > 0; off >>= 1)
        partial += __shfl_down_sync(0xffffffffu, partial, off);
    if ((t & 31) == 0) s_w[t >> 5] = partial;
    __syncthreads();
    if (t == 0) s_den = s_w[0] + s_w[1] + s_w[2] + s_w[3];
    __syncthreads();
    float inv = 1.f / (s_den + 1e-16f);

    int eh = t >> 6, p = t & 63;
    float2 a0 = {0.f, 0.f}, a1 = {0.f, 0.f}, a2 = {0.f, 0.f}, a3 = {0.f, 0.f};

    auto step = [&](int i, float2& a) {
        float ex; int src;
        if (i < CAP2) { ex = s_ex[i]; src = s_src[i]; }
        else {
            float4 f = g_csr[(size_t)(base + i) * 2];
            src = __float_as_int(f.x);
            float al = g_as2[src] + ad + f.y;
            al = (al > 0.f) ? al : NEG * al;
            ex = __expf(al);
        }
        uint32_t raw = g_xh2b[(size_t)src * 64 + p];
        __nv_bfloat162 bv = *(__nv_bfloat162*)&raw;
        float2 fv = __bfloat1622float2(bv);
        a.x = fmaf(ex, fv.x, a.x);
        a.y = fmaf(ex, fv.y, a.y);
    };

    int i = eh;
    for (; i + 6 < deg; i += 8) {
        step(i, a0); step(i + 2, a1); step(i + 4, a2); step(i + 6, a3);
    }
    for (; i < deg; i += 2) step(i, a0);
    a0.x = (a0.x + a1.x) + (a2.x + a3.x);
    a0.y = (a0.y + a1.y) + (a2.y + a3.y);

    s_half[eh][p] = a0;
    __syncthreads();

    if (t < 64) {
        float2 hA = s_half[0][t], hB = s_half[1][t];
        float h0 = (hA.x + hB.x) * inv;
        float h1 = (hA.y + hB.y) * inv;
        float2 bb = *(const float2*)&b2[2 * t];
        h0 += bb.x; h1 += bb.y;
        h0 = (h0 > 0.f) ? h0 : 0.f;
        h1 = (h1 > 0.f) ? h1 : 0.f;
        float2 wf = *(const float2*)&Wfc[2 * t];
        float part = fmaf(h0, wf.x, h1 * wf.y);
        for (int off = 16; off > 0; off >>= 1)
            part += __shfl_down_sync(0xffffffffu, part, off);
        if ((t & 31) == 0) s_red[t >> 5] = part;
    }
    __syncthreads();
    if (t == 0) {
        float z = s_red[0] + s_red[1] + bfc[0];
        out[n] = 1.f / (1.f + __expf(-z));
    }
}

// ---------------- launcher -------------------------------------------------

extern "C" void kernel_launch(void* const* d_in, const int* in_sizes, int n_in,
                              void* d_out, int out_size) {
    const float* x    = (const float*)d_in[0];
    const int*   ei   = (const int*)  d_in[1];
    const float* ea   = (const float*)d_in[2];
    const float* W1   = (const float*)d_in[3];
    const float* We1  = (const float*)d_in[4];
    const float* as1v = (const float*)d_in[5];
    const float* ad1v = (const float*)d_in[6];
    const float* ae1v = (const float*)d_in[7];
    const float* b1   = (const float*)d_in[8];
    const float* W2   = (const float*)d_in[9];
    const float* We2  = (const float*)d_in[10];
    const float* as2v = (const float*)d_in[11];
    const float* ad2v = (const float*)d_in[12];
    const float* ae2v = (const float*)d_in[13];
    const float* b2   = (const float*)d_in[14];
    const float* Wfc  = (const float*)d_in[15];
    const float* bfc  = (const float*)d_in[16];
    float* out = (float*)d_out;

    static void* p_deg = nullptr;
    static void* p_flag = nullptr;
    if (!p_deg) {
        cudaFuncSetAttribute(k_gemm, cudaFuncAttributeMaxDynamicSharedMemorySize, GSM_TOTAL);
        cudaGetSymbolAddress(&p_deg, g_deg);
        cudaGetSymbolAddress(&p_flag, g_flag);
    }

    cudaMemsetAsync(p_deg, 0, Nn * sizeof(int));
    cudaMemsetAsync(p_flag, 0, SC_BLOCKS * sizeof(int));
    k_init<<<IB_TOTAL, 256>>>(ea, W2, ei, W1, We1, We2,
                              as1v, ad1v, ae1v, as2v, ad2v, ae2v);
    k_preE<<<1, 384>>>();
    k_scan1<<<SC_BLOCKS, 256>>>();
    k_node1<<<(Nn * 8 + 255) / 256, 256>>>(x);
    k_scatter<<<(ET + 255) / 256, 256>>>(ei, ea);
    k_agg1<<<Nn / 8, 256>>>(W1, b1);
    k_gemm<<<MROWS / 128, 256, GSM_TOTAL>>>();
    k_agg2<<<Nn, 128>>>(b2, Wfc, bfc, out);
}

// round 13
// speedup vs baseline: 1.4362x; 1.2183x over previous
#include <cuda_runtime.h>
#include <cuda_bf16.h>
#include <mma.h>
#include <cstdint>

using namespace nvcuda;

#define Nn 40000
#define Ee 640000
#define ET 680000   /* Ee + Nn self loops */
#define HIDc 128
#define H1c 4
#define D1 512      /* H1*HID */
#define IND 5
#define EDD 11
#define NEG 0.2f

#define EAP_BLOCKS 640
#define EAP_ROWS 1000

#define MROWS 40064          /* 313 * 128, padded M */
#define SC_BLOCKS 157        /* ceil(40000/256) scan blocks */

/* k_init block ranges */
#define IB_EAP  640
#define IB_W2   256
#define IB_CNT  2657         /* ceil(680000/256) */
#define IB_US2  128          /* 1024 warp-outputs: us2/ud2 */
#define IB_MISC 12           /* 95 warp-outputs: aev1,aev2,us1,ud1 */
#define IB_TOTAL (IB_EAP + IB_W2 + IB_CNT + IB_US2 + IB_MISC)

// ---------------- scratch (device globals; no allocation allowed) ----------
__device__ __nv_bfloat16 g_h1b[(size_t)MROWS * D1];     // padded rows stay zero
__device__ uint32_t g_xh2b[(size_t)MROWS * 64];         // bf16x2 packed
__device__ __nv_bfloat16 g_W2b[D1 * HIDc];
__device__ float g_x8[(size_t)Nn * 8];                  // padded x rows (32B)
__device__ float g_as1[Nn * H1c];
__device__ float g_ad1[Nn * H1c];
__device__ float g_as2[Nn];
__device__ float g_ad2[Nn];
__device__ int   g_deg[Nn];
__device__ int   g_rowstart[Nn + 1];
__device__ int   g_cursor[Nn];
__device__ int   g_flag[SC_BLOCKS];
__device__ int   g_aggv[SC_BLOCKS];
__device__ int   g_inclv[SC_BLOCKS];
__device__ float4 g_csr[(size_t)ET * 2];   // AoS: {src,e2,a1_0,a1_1},{a1_2,a1_3,-,-}
__device__ float g_eamean[EDD];
__device__ float g_eapart[EAP_BLOCKS * EDD];
__device__ float g_aev1[H1c * EDD];
__device__ float g_aev2[EDD];
__device__ float g_us1[H1c * IND];
__device__ float g_ud1[H1c * IND];
__device__ float g_us2[D1];
__device__ float g_ud2[D1];

// ---------------- small helpers --------------------------------------------
__device__ __forceinline__ uint32_t smem_u32(const void* p) {
    uint32_t a;
    asm("{ .reg .u64 t; cvta.to.shared.u64 t, %1; cvt.u32.u64 %0, t; }" : "=r"(a) : "l"(p));
    return a;
}
__device__ __forceinline__ void cp_async16(uint32_t dst, const void* src) {
    asm volatile("cp.async.cg.shared.global [%0], [%1], 16;" :: "r"(dst), "l"(src));
}
#define CP_COMMIT() asm volatile("cp.async.commit_group;" ::: "memory")
#define CP_WAIT1()  asm volatile("cp.async.wait_group 1;" ::: "memory")
#define CP_WAIT0()  asm volatile("cp.async.wait_group 0;" ::: "memory")

__device__ __forceinline__ float warp_red(float v) {
#pragma unroll
    for (int off = 16; off > 0; off >>= 1)
        v += __shfl_down_sync(0xffffffffu, v, off);
    return v;
}

__device__ __forceinline__ float warp_dot128(const float* a, const float* b, int lane) {
    float s = 0.f;
#pragma unroll
    for (int c = 0; c < 4; c++) s = fmaf(a[lane + 32 * c], b[lane + 32 * c], s);
    return warp_red(s);
}

// block-wide inclusive scan helper (256 threads)
__device__ __forceinline__ int block_scan_incl(int v, int t, int* total_out) {
    int lane = t & 31, w = t >> 5;
    int sv = v;
#pragma unroll
    for (int off = 1; off < 32; off <<= 1) {
        int nv = __shfl_up_sync(0xffffffffu, sv, off);
        if (lane >= off) sv += nv;
    }
    __shared__ int ws[8];
    __shared__ int wo[8];
    __shared__ int tot;
    if (lane == 31) ws[w] = sv;
    __syncthreads();
    if (t == 0) {
        int run = 0;
#pragma unroll
        for (int k = 0; k < 8; k++) { wo[k] = run; run += ws[k]; }
        tot = run;
    }
    __syncthreads();
    *total_out = tot;
    return sv + wo[w];
}

// ---------------- kernels --------------------------------------------------

// fused: ea partial sums | W2->bf16 | degree count | u/aev precompute (warp-per-output)
__global__ void k_init(const float* __restrict__ ea,  const float* __restrict__ W2,
                       const int*   __restrict__ ei,
                       const float* __restrict__ W1,  const float* __restrict__ We1,
                       const float* __restrict__ We2,
                       const float* __restrict__ as1, const float* __restrict__ ad1,
                       const float* __restrict__ ae1,
                       const float* __restrict__ as2, const float* __restrict__ ad2,
                       const float* __restrict__ ae2) {
    int b = blockIdx.x, t = threadIdx.x;
    if (b < IB_EAP) {
        __shared__ float sm[256 * EDD];
        float loc[EDD];
#pragma unroll
        for (int d = 0; d < EDD; d++) loc[d] = 0.f;
        int r0 = b * EAP_ROWS;
        for (int r = t; r < EAP_ROWS; r += 256) {
            const float* p = ea + (size_t)(r0 + r) * EDD;
#pragma unroll
            for (int d = 0; d < EDD; d++) loc[d] += p[d];
        }
#pragma unroll
        for (int d = 0; d < EDD; d++) sm[t * EDD + d] = loc[d];
        __syncthreads();
        for (int off = 128; off > 0; off >>= 1) {
            if (t < off) {
#pragma unroll
                for (int d = 0; d < EDD; d++) sm[t * EDD + d] += sm[(t + off) * EDD + d];
            }
            __syncthreads();
        }
        if (t < EDD) g_eapart[b * EDD + t] = sm[t];
    } else if (b < IB_EAP + IB_W2) {
        int idx = (b - IB_EAP) * 256 + t;
        g_W2b[idx] = __float2bfloat16(W2[idx]);
    } else if (b < IB_EAP + IB_W2 + IB_CNT) {
        int e = (b - IB_EAP - IB_W2) * 256 + t;
        if (e < ET) {
            int d = (e < Ee) ? ei[Ee + e] : (e - Ee);
            atomicAdd(&g_deg[d], 1);
        }
    } else if (b < IB_EAP + IB_W2 + IB_CNT + IB_US2) {
        int g = (b - IB_EAP - IB_W2 - IB_CNT) * 8 + (t >> 5);   // 0..1023
        int lane = t & 31;
        if (g < 512) {
            float s = warp_dot128(W2 + (size_t)g * HIDc, as2, lane);
            if (lane == 0) g_us2[g] = s;
        } else {
            int k = g - 512;
            float s = warp_dot128(W2 + (size_t)k * HIDc, ad2, lane);
            if (lane == 0) g_ud2[k] = s;
        }
    } else {
        int g = (b - IB_EAP - IB_W2 - IB_CNT - IB_US2) * 8 + (t >> 5);  // 0..95
        int lane = t & 31;
        if (g < 44) {                       // aev1[h][d]
            int h = g / EDD, d = g % EDD;
            float s = 0.f;
#pragma unroll
            for (int c = 0; c < 4; c++)
                s = fmaf(We1[d * D1 + h * HIDc + lane + 32 * c],
                         ae1[h * HIDc + lane + 32 * c], s);
            s = warp_red(s);
            if (lane == 0) g_aev1[g] = s;
        } else if (g < 55) {                // aev2[d]
            int d = g - 44;
            float s = warp_dot128(We2 + (size_t)d * HIDc, ae2, lane);
            if (lane == 0) g_aev2[d] = s;
        } else if (g < 75) {                // us1[h*5+d]
            int o = g - 55, h = o / IND, d = o % IND;
            float s = 0.f;
#pragma unroll
            for (int c = 0; c < 4; c++)
                s = fmaf(W1[d * D1 + h * HIDc + lane + 32 * c],
                         as1[h * HIDc + lane + 32 * c], s);
            s = warp_red(s);
            if (lane == 0) g_us1[o] = s;
        } else if (g < 95) {                // ud1[h*5+d]
            int o = g - 75, h = o / IND, d = o % IND;
            float s = 0.f;
#pragma unroll
            for (int c = 0; c < 4; c++)
                s = fmaf(W1[d * D1 + h * HIDc + lane + 32 * c],
                         ad1[h * HIDc + lane + 32 * c], s);
            s = warp_red(s);
            if (lane == 0) g_ud1[o] = s;
        }
    }
}

// eamean from partials (warp per column)
__global__ void k_preE() {
    int w = threadIdx.x >> 5, lane = threadIdx.x & 31;
    if (w >= EDD) return;
    float s = 0.f;
    for (int b = lane; b < EAP_BLOCKS; b += 32) s += g_eapart[b * EDD + w];
    s = warp_red(s);
    if (lane == 0) g_eamean[w] = s / (float)Ee;
}

// single-pass decoupled-lookback scan of deg -> rowstart, cursor
__global__ void k_scan1() {
    int b = blockIdx.x, t = threadIdx.x;
    int i = b * 256 + t;
    int v = (i < Nn) ? g_deg[i] : 0;
    int tot;
    int incl = block_scan_incl(v, t, &tot);
    __shared__ int s_off;
    volatile int* flag = g_flag;
    volatile int* aggv = g_aggv;
    volatile int* inclv = g_inclv;
    if (t == 0) {
        if (b == 0) {
            inclv[0] = tot; __threadfence(); flag[0] = 2;
            s_off = 0;
        } else {
            aggv[b] = tot; __threadfence(); flag[b] = 1;
            int run = 0, j = b - 1;
            while (true) {
                int f;
                do { f = flag[j]; } while (f == 0);
                if (f == 2) { run += inclv[j]; break; }
                run += aggv[j]; j--;
            }
            inclv[b] = run + tot; __threadfence(); flag[b] = 2;
            s_off = run;
        }
    }
    __syncthreads();
    int r = s_off + incl - v;
    if (i < Nn) { g_rowstart[i] = r; g_cursor[i] = r; }
    if (b == SC_BLOCKS - 1 && t == 255) g_rowstart[Nn] = ET;
}

// attention scalars + padded x rows (8 threads per node)
__global__ void k_node1(const float* __restrict__ x) {
    int idx = blockIdx.x * blockDim.x + threadIdx.x;
    int n = idx >> 3;
    if (n >= Nn) return;
    int r = idx & 7;
    int h = r & 3;
    const float* xp = x + (size_t)n * IND;
    g_x8[(size_t)n * 8 + r] = (r < IND) ? xp[r] : 0.f;
    const float* u = (r < 4) ? (g_us1 + h * IND) : (g_ud1 + h * IND);
    float s = 0.f;
#pragma unroll
    for (int d = 0; d < IND; d++) s += xp[d] * u[d];
    if (r < 4) g_as1[n * H1c + h] = s;
    else       g_ad1[n * H1c + h] = s;
}

__global__ void k_scatter(const int* __restrict__ ei, const float* __restrict__ ea) {
    int e = blockIdx.x * blockDim.x + threadIdx.x;
    if (e >= ET) return;
    int s, d;
    float v[EDD];
    if (e < Ee) {
        s = ei[e]; d = ei[Ee + e];
        const float* p = ea + (size_t)e * EDD;
#pragma unroll
        for (int k = 0; k < EDD; k++) v[k] = p[k];
    } else {
        s = e - Ee; d = s;
#pragma unroll
        for (int k = 0; k < EDD; k++) v[k] = g_eamean[k];
    }
    int pos = atomicAdd(&g_cursor[d], 1);
    float e2 = 0.f;
#pragma unroll
    for (int k = 0; k < EDD; k++) e2 += v[k] * g_aev2[k];

    float4 asv = *(const float4*)&g_as1[s * H1c];
    float4 adv = *(const float4*)&g_ad1[d * H1c];
    float al[H1c];
#pragma unroll
    for (int h = 0; h < H1c; h++) {
        float ed = 0.f;
#pragma unroll
        for (int k = 0; k < EDD; k++) ed += v[k] * g_aev1[h * EDD + k];
        float a = ((h == 0) ? asv.x : (h == 1) ? asv.y : (h == 2) ? asv.z : asv.w)
                + ((h == 0) ? adv.x : (h == 1) ? adv.y : (h == 2) ? adv.z : adv.w) + ed;
        al[h] = (a > 0.f) ? a : NEG * a;
    }
    g_csr[(size_t)pos * 2]     = make_float4(__int_as_float(s), e2, al[0], al[1]);
    g_csr[(size_t)pos * 2 + 1] = make_float4(al[2], al[3], 0.f, 0.f);
}

// layer-1 softmax + aggregation + projection, three-phase (R12 form)
__global__ __launch_bounds__(256) void k_agg1(const float* __restrict__ W1,
                                              const float* __restrict__ b1) {
    __shared__ float s_ax[8][21];
    __shared__ uint32_t s_h1[8][256];       // bf16x2 packed, 8 KB
    __shared__ float s_u[D1];
    __shared__ float s_ud[D1];
    int t = threadIdx.x;
    int w = t >> 5, lane = t & 31;
    int n0 = blockIdx.x * 8;
    int n = n0 + w;                         // Nn % 8 == 0

#pragma unroll
    for (int i = 0; i < 2; i++) {
        s_u [t + i * 256] = g_us2[t + i * 256];
        s_ud[t + i * 256] = g_ud2[t + i * 256];
    }

    int base = g_rowstart[n];
    int deg  = g_rowstart[n + 1] - base;

    float den[H1c];
    float ax[H1c][IND];
#pragma unroll
    for (int h = 0; h < H1c; h++) {
        den[h] = 0.f;
#pragma unroll
        for (int d = 0; d < IND; d++) ax[h][d] = 0.f;
    }

    for (int i = lane; i < deg; i += 32) {
        float4 fa = g_csr[(size_t)(base + i) * 2];
        float4 fb = g_csr[(size_t)(base + i) * 2 + 1];
        int src = __float_as_int(fa.x);
        float e0 = __expf(fa.z), e1 = __expf(fa.w), e2 = __expf(fb.x), e3 = __expf(fb.y);
        den[0] += e0; den[1] += e1; den[2] += e2; den[3] += e3;
        const float* xp = g_x8 + (size_t)src * 8;
        float4 xv4 = __ldg((const float4*)xp);
        float xv5 = __ldg(xp + 4);
        float xv[IND] = {xv4.x, xv4.y, xv4.z, xv4.w, xv5};
#pragma unroll
        for (int d = 0; d < IND; d++) {
            ax[0][d] = fmaf(e0, xv[d], ax[0][d]);
            ax[1][d] = fmaf(e1, xv[d], ax[1][d]);
            ax[2][d] = fmaf(e2, xv[d], ax[2][d]);
            ax[3][d] = fmaf(e3, xv[d], ax[3][d]);
        }
    }
#pragma unroll
    for (int off = 16; off > 0; off >>= 1) {
#pragma unroll
        for (int h = 0; h < H1c; h++) {
            den[h] += __shfl_xor_sync(0xffffffffu, den[h], off);
#pragma unroll
            for (int d = 0; d < IND; d++)
                ax[h][d] += __shfl_xor_sync(0xffffffffu, ax[h][d], off);
        }
    }
    if (lane < 20) {
        int h = lane / IND, d = lane % IND;
        s_ax[w][lane] = ax[h][d] * (1.f / (den[h] + 1e-16f));
    }
    __syncthreads();

    int c0 = t * 2;
    int h2 = c0 >> 7;
    float2 wv[IND];
#pragma unroll
    for (int d = 0; d < IND; d++) wv[d] = *(const float2*)&W1[d * D1 + c0];
    float2 bb = *(const float2*)&b1[c0];

#pragma unroll
    for (int q = 0; q < 8; q++) {
        float a0 = bb.x, a1 = bb.y;
#pragma unroll
        for (int d = 0; d < IND; d++) {
            float av = s_ax[q][h2 * IND + d];
            a0 = fmaf(av, wv[d].x, a0);
            a1 = fmaf(av, wv[d].y, a1);
        }
        a0 = (a0 > 0.f) ? a0 : 0.f;
        a1 = (a1 > 0.f) ? a1 : 0.f;
        __nv_bfloat162 bv = __float22bfloat162_rn(make_float2(a0, a1));
        *(__nv_bfloat162*)(g_h1b + (size_t)(n0 + q) * D1 + c0) = bv;
        s_h1[q][t] = *(uint32_t*)&bv;
    }
    __syncthreads();

    float s2 = 0.f, d2v = 0.f;
#pragma unroll
    for (int j = 0; j < 8; j++) {
        int c = j * 32 + lane;
        uint32_t raw = s_h1[w][c];
        float2 f = __bfloat1622float2(*(__nv_bfloat162*)&raw);
        s2  = fmaf(f.x, s_u [2 * c], fmaf(f.y, s_u [2 * c + 1], s2));
        d2v = fmaf(f.x, s_ud[2 * c], fmaf(f.y, s_ud[2 * c + 1], d2v));
    }
    s2  = warp_red(s2);
    d2v = warp_red(d2v);
    if (lane == 0) { g_as2[n] = s2; g_ad2[n] = d2v; }
}

// xh2 = h1 @ W2 : bf16 wmma (HMMA), 128x128 CTA tile, K chunks of 64,
// cp.async double-buffered; bf16x2 packed output staged through smem.
#define KC 64
#define A_ELEMS 9216    /* 128 * 72 */
#define B_ELEMS 8704    /* 64 * 136 */
#define A_BYTES 18432
#define B_BYTES 17408
#define GSM_TOTAL (2 * (A_BYTES + B_BYTES))   /* 71680 >= 65536 for C staging */

__global__ __launch_bounds__(256, 2) void k_gemm() {
    extern __shared__ char smc[];
    __nv_bfloat16* As = (__nv_bfloat16*)smc;                     // [2][128][72]
    __nv_bfloat16* Bs = (__nv_bfloat16*)(smc + 2 * A_BYTES);     // [2][64][136]
    uint32_t smA = smem_u32(As);
    uint32_t smB = smem_u32(Bs);

    int t = threadIdx.x;
    int wid = t >> 5;
    int row0 = blockIdx.x * 128;
    int wm0 = (wid >> 2) * 64;     // 0 or 64
    int wn0 = (wid & 3) * 32;      // 0,32,64,96

    wmma::fragment<wmma::accumulator, 16, 16, 16, float> acc[4][2];
#pragma unroll
    for (int m = 0; m < 4; m++)
#pragma unroll
        for (int n = 0; n < 2; n++) wmma::fill_fragment(acc[m][n], 0.f);

    auto load_chunk = [&](int buf, int k0) {
#pragma unroll
        for (int i = 0; i < 4; i++) {
            int v = i * 256 + t;
            int r = v >> 3, c8 = v & 7;                 // A: 128 rows x 8 uint4
            cp_async16(smA + (uint32_t)(buf * A_ELEMS + r * 72 + c8 * 8) * 2,
                       g_h1b + (size_t)(row0 + r) * D1 + k0 + c8 * 8);
        }
#pragma unroll
        for (int i = 0; i < 4; i++) {
            int v = i * 256 + t;
            int r = v >> 4, c8 = v & 15;                // B: 64 rows x 16 uint4
            cp_async16(smB + (uint32_t)(buf * B_ELEMS + r * 136 + c8 * 8) * 2,
                       g_W2b + (size_t)(k0 + r) * HIDc + c8 * 8);
        }
        CP_COMMIT();
    };

    load_chunk(0, 0);
    int buf = 0;
#pragma unroll
    for (int c = 0; c < 8; c++) {
        if (c < 7) load_chunk(buf ^ 1, (c + 1) * KC);
        if (c < 7) CP_WAIT1(); else CP_WAIT0();
        __syncthreads();

        const __nv_bfloat16* Ab = As + buf * A_ELEMS;
        const __nv_bfloat16* Bb = Bs + buf * B_ELEMS;
#pragma unroll
        for (int kk = 0; kk < 4; kk++) {
            wmma::fragment<wmma::matrix_a, 16, 16, 16, __nv_bfloat16, wmma::row_major> af[4];
            wmma::fragment<wmma::matrix_b, 16, 16, 16, __nv_bfloat16, wmma::row_major> bf[2];
#pragma unroll
            for (int m = 0; m < 4; m++)
                wmma::load_matrix_sync(af[m], Ab + (wm0 + m * 16) * 72 + kk * 16, 72);
#pragma unroll
            for (int n = 0; n < 2; n++)
                wmma::load_matrix_sync(bf[n], Bb + (kk * 16) * 136 + wn0 + n * 16, 136);
#pragma unroll
            for (int m = 0; m < 4; m++)
#pragma unroll
                for (int n = 0; n < 2; n++)
                    wmma::mma_sync(acc[m][n], af[m], bf[n], acc[m][n]);
        }
        __syncthreads();
        buf ^= 1;
    }

    // stage fp32 C in smem, emit packed bf16x2
    float* Cs = (float*)smc;    // 128*128 fp32 = 64KB
#pragma unroll
    for (int m = 0; m < 4; m++)
#pragma unroll
        for (int n = 0; n < 2; n++)
            wmma::store_matrix_sync(Cs + (size_t)(wm0 + m * 16) * 128 + wn0 + n * 16,
                                    acc[m][n], 128, wmma::mem_row_major);
    __syncthreads();
#pragma unroll
    for (int j = 0; j < 32; j++) {
        int idx = j * 256 + t;          // 8192 bf16x2 pairs
        int row = idx >> 6, cp = idx & 63;
        float2 f = *(const float2*)&Cs[row * 128 + cp * 2];
        __nv_bfloat162 bv = __float22bfloat162_rn(f);
        g_xh2b[(size_t)(row0 + row) * 64 + cp] = *(uint32_t*)&bv;
    }
}

// layer-2 softmax + aggregation + final linear + sigmoid, warp-per-node.
// No block barriers: per-lane edge registers + shfl broadcast gather.
__global__ __launch_bounds__(256) void k_agg2(const float* __restrict__ b2,
                                              const float* __restrict__ Wfc,
                                              const float* __restrict__ bfc,
                                              float* __restrict__ out) {
    int t = threadIdx.x;
    int w = t >> 5, lane = t & 31;
    int n = blockIdx.x * 8 + w;            // Nn % 8 == 0
    int base = g_rowstart[n];
    int deg  = g_rowstart[n + 1] - base;
    float ad = g_ad2[n];

    float acc0 = 0.f, acc1 = 0.f, acc2 = 0.f, acc3 = 0.f;
    float den = 0.f;

    for (int b0 = 0; b0 < deg; b0 += 32) {
        float ex = 0.f; int src = 0;
        int i = b0 + lane;
        if (i < deg) {
            float4 f = g_csr[(size_t)(base + i) * 2];
            src = __float_as_int(f.x);
            float al = g_as2[src] + ad + f.y;
            al = (al > 0.f) ? al : NEG * al;
            ex = __expf(al);
        }
        den += ex;
        int cnt = deg - b0; if (cnt > 32) cnt = 32;
        for (int j = 0; j < cnt; j++) {
            float exj = __shfl_sync(0xffffffffu, ex, j);
            int srcj  = __shfl_sync(0xffffffffu, src, j);
            uint2 raw = *(const uint2*)&g_xh2b[(size_t)srcj * 64 + lane * 2];
            float2 f0 = __bfloat1622float2(*(__nv_bfloat162*)&raw.x);
            float2 f1 = __bfloat1622float2(*(__nv_bfloat162*)&raw.y);
            acc0 = fmaf(exj, f0.x, acc0);
            acc1 = fmaf(exj, f0.y, acc1);
            acc2 = fmaf(exj, f1.x, acc2);
            acc3 = fmaf(exj, f1.y, acc3);
        }
    }
#pragma unroll
    for (int off = 16; off > 0; off >>= 1)
        den += __shfl_xor_sync(0xffffffffu, den, off);
    float inv = 1.f / (den + 1e-16f);

    float4 bb = *(const float4*)&b2[lane * 4];
    float4 wf = *(const float4*)&Wfc[lane * 4];
    float h0 = acc0 * inv + bb.x; h0 = (h0 > 0.f) ? h0 : 0.f;
    float h1 = acc1 * inv + bb.y; h1 = (h1 > 0.f) ? h1 : 0.f;
    float h2 = acc2 * inv + bb.z; h2 = (h2 > 0.f) ? h2 : 0.f;
    float h3 = acc3 * inv + bb.w; h3 = (h3 > 0.f) ? h3 : 0.f;
    float part = fmaf(h0, wf.x, fmaf(h1, wf.y, fmaf(h2, wf.z, h3 * wf.w)));
    part = warp_red(part);
    if (lane == 0) {
        float z = part + bfc[0];
        out[n] = 1.f / (1.f + __expf(-z));
    }
}

// ---------------- launcher -------------------------------------------------

extern "C" void kernel_launch(void* const* d_in, const int* in_sizes, int n_in,
                              void* d_out, int out_size) {
    const float* x    = (const float*)d_in[0];
    const int*   ei   = (const int*)  d_in[1];
    const float* ea   = (const float*)d_in[2];
    const float* W1   = (const float*)d_in[3];
    const float* We1  = (const float*)d_in[4];
    const float* as1v = (const float*)d_in[5];
    const float* ad1v = (const float*)d_in[6];
    const float* ae1v = (const float*)d_in[7];
    const float* b1   = (const float*)d_in[8];
    const float* W2   = (const float*)d_in[9];
    const float* We2  = (const float*)d_in[10];
    const float* as2v = (const float*)d_in[11];
    const float* ad2v = (const float*)d_in[12];
    const float* ae2v = (const float*)d_in[13];
    const float* b2   = (const float*)d_in[14];
    const float* Wfc  = (const float*)d_in[15];
    const float* bfc  = (const float*)d_in[16];
    float* out = (float*)d_out;

    static void* p_deg = nullptr;
    static void* p_flag = nullptr;
    if (!p_deg) {
        cudaFuncSetAttribute(k_gemm, cudaFuncAttributeMaxDynamicSharedMemorySize, GSM_TOTAL);
        cudaGetSymbolAddress(&p_deg, g_deg);
        cudaGetSymbolAddress(&p_flag, g_flag);
    }

    cudaMemsetAsync(p_deg, 0, Nn * sizeof(int));
    cudaMemsetAsync(p_flag, 0, SC_BLOCKS * sizeof(int));
    k_init<<<IB_TOTAL, 256>>>(ea, W2, ei, W1, We1, We2,
                              as1v, ad1v, ae1v, as2v, ad2v, ae2v);
    k_preE<<<1, 384>>>();
    k_scan1<<<SC_BLOCKS, 256>>>();
    k_node1<<<(Nn * 8 + 255) / 256, 256>>>(x);
    k_scatter<<<(ET + 255) / 256, 256>>>(ei, ea);
    k_agg1<<<Nn / 8, 256>>>(W1, b1);
    k_gemm<<<MROWS / 128, 256, GSM_TOTAL>>>();
    k_agg2<<<Nn / 8, 256>>>(b2, Wfc, bfc, out);
}

// round 14
// speedup vs baseline: 1.4545x; 1.0127x over previous
#include <cuda_runtime.h>
#include <cuda_bf16.h>
#include <mma.h>
#include <cstdint>

using namespace nvcuda;

#define Nn 40000
#define Ee 640000
#define ET 680000   /* Ee + Nn self loops */
#define HIDc 128
#define H1c 4
#define D1 512      /* H1*HID */
#define IND 5
#define EDD 11
#define NEG 0.2f

#define EAP_BLOCKS 160
#define EAP_ROWS 4000

#define MROWS 40064          /* 313 * 128, padded M */
#define SC_BLOCKS 157        /* ceil(40000/256) scan blocks */
#define N1_BLOCKS 1250       /* node1 blocks */

/* k_init block ranges */
#define IB_EAP  160
#define IB_W2   64           /* 65536 / (256*4) */
#define IB_CNT  665          /* ceil(680000/(256*4)) */
#define IB_US2  128          /* 1024 warp-outputs: us2/ud2 */
#define IB_MISC 12           /* 95 warp-outputs: aev1,aev2,us1,ud1 */
#define IB_TOTAL (IB_EAP + IB_W2 + IB_CNT + IB_US2 + IB_MISC)

// ---------------- scratch (device globals; no allocation allowed) ----------
__device__ __nv_bfloat16 g_h1b[(size_t)MROWS * D1];     // padded rows stay zero
__device__ uint32_t g_xh2b[(size_t)MROWS * 64];         // bf16x2 packed
__device__ __nv_bfloat16 g_W2b[D1 * HIDc];
__device__ float g_x8[(size_t)Nn * 8];                  // padded x rows (32B)
__device__ float g_as1[Nn * H1c];
__device__ float g_ad1[Nn * H1c];
__device__ float g_as2[Nn];
__device__ float g_ad2[Nn];
__device__ int   g_deg[Nn];
__device__ int   g_rowstart[Nn + 1];
__device__ int   g_cursor[Nn];
__device__ int   g_flag[SC_BLOCKS];
__device__ int   g_aggv[SC_BLOCKS];
__device__ int   g_inclv[SC_BLOCKS];
__device__ float4 g_csr[(size_t)ET * 2];   // AoS: {src,e2,a1_0,a1_1},{a1_2,a1_3,-,-}
__device__ float g_eamean[EDD];
__device__ float g_eapart[EAP_BLOCKS * EDD];
__device__ float g_aev1[H1c * EDD];
__device__ float g_aev2[EDD];
__device__ float g_us1[H1c * IND];
__device__ float g_ud1[H1c * IND];
__device__ float g_us2[D1];
__device__ float g_ud2[D1];

// ---------------- small helpers --------------------------------------------
__device__ __forceinline__ uint32_t smem_u32(const void* p) {
    uint32_t a;
    asm("{ .reg .u64 t; cvta.to.shared.u64 t, %1; cvt.u32.u64 %0, t; }" : "=r"(a) : "l"(p));
    return a;
}
__device__ __forceinline__ void cp_async16(uint32_t dst, const void* src) {
    asm volatile("cp.async.cg.shared.global [%0], [%1], 16;" :: "r"(dst), "l"(src));
}
#define CP_COMMIT() asm volatile("cp.async.commit_group;" ::: "memory")
#define CP_WAIT1()  asm volatile("cp.async.wait_group 1;" ::: "memory")
#define CP_WAIT0()  asm volatile("cp.async.wait_group 0;" ::: "memory")

__device__ __forceinline__ float warp_red(float v) {
#pragma unroll
    for (int off = 16; off > 0; off >>= 1)
        v += __shfl_down_sync(0xffffffffu, v, off);
    return v;
}

__device__ __forceinline__ float warp_dot128(const float* a, const float* b, int lane) {
    float s = 0.f;
#pragma unroll
    for (int c = 0; c < 4; c++) s = fmaf(a[lane + 32 * c], b[lane + 32 * c], s);
    return warp_red(s);
}

// block-wide inclusive scan helper (256 threads)
__device__ __forceinline__ int block_scan_incl(int v, int t, int* total_out) {
    int lane = t & 31, w = t >> 5;
    int sv = v;
#pragma unroll
    for (int off = 1; off < 32; off <<= 1) {
        int nv = __shfl_up_sync(0xffffffffu, sv, off);
        if (lane >= off) sv += nv;
    }
    __shared__ int ws[8];
    __shared__ int wo[8];
    __shared__ int tot;
    if (lane == 31) ws[w] = sv;
    __syncthreads();
    if (t == 0) {
        int run = 0;
#pragma unroll
        for (int k = 0; k < 8; k++) { wo[k] = run; run += ws[k]; }
        tot = run;
    }
    __syncthreads();
    *total_out = tot;
    return sv + wo[w];
}

// ---------------- kernels --------------------------------------------------

// fused: ea partial sums | W2->bf16 | degree count | u/aev precompute
__global__ void k_init(const float* __restrict__ ea,  const float* __restrict__ W2,
                       const int*   __restrict__ ei,
                       const float* __restrict__ W1,  const float* __restrict__ We1,
                       const float* __restrict__ We2,
                       const float* __restrict__ as1, const float* __restrict__ ad1,
                       const float* __restrict__ ae1,
                       const float* __restrict__ as2, const float* __restrict__ ad2,
                       const float* __restrict__ ae2) {
    int b = blockIdx.x, t = threadIdx.x;
    if (b < IB_EAP) {
        __shared__ float sm[256 * EDD];
        float loc[EDD];
#pragma unroll
        for (int d = 0; d < EDD; d++) loc[d] = 0.f;
        int r0 = b * EAP_ROWS;
        for (int r = t; r < EAP_ROWS; r += 256) {
            const float* p = ea + (size_t)(r0 + r) * EDD;
#pragma unroll
            for (int d = 0; d < EDD; d++) loc[d] += p[d];
        }
#pragma unroll
        for (int d = 0; d < EDD; d++) sm[t * EDD + d] = loc[d];
        __syncthreads();
        for (int off = 128; off > 0; off >>= 1) {
            if (t < off) {
#pragma unroll
                for (int d = 0; d < EDD; d++) sm[t * EDD + d] += sm[(t + off) * EDD + d];
            }
            __syncthreads();
        }
        if (t < EDD) g_eapart[b * EDD + t] = sm[t];
    } else if (b < IB_EAP + IB_W2) {
        int idx = ((b - IB_EAP) * 256 + t) * 4;
        float4 v = *(const float4*)&W2[idx];
        __nv_bfloat162 lo = __float22bfloat162_rn(make_float2(v.x, v.y));
        __nv_bfloat162 hi = __float22bfloat162_rn(make_float2(v.z, v.w));
        *(uint2*)&g_W2b[idx] = make_uint2(*(uint32_t*)&lo, *(uint32_t*)&hi);
    } else if (b < IB_EAP + IB_W2 + IB_CNT) {
        int e0 = ((b - IB_EAP - IB_W2) * 256 + t) * 4;
#pragma unroll
        for (int k = 0; k < 4; k++) {
            int e = e0 + k;
            if (e < ET) {
                int d = (e < Ee) ? ei[Ee + e] : (e - Ee);
                atomicAdd(&g_deg[d], 1);
            }
        }
    } else if (b < IB_EAP + IB_W2 + IB_CNT + IB_US2) {
        int g = (b - IB_EAP - IB_W2 - IB_CNT) * 8 + (t >> 5);   // 0..1023
        int lane = t & 31;
        if (g < 512) {
            float s = warp_dot128(W2 + (size_t)g * HIDc, as2, lane);
            if (lane == 0) g_us2[g] = s;
        } else {
            int k = g - 512;
            float s = warp_dot128(W2 + (size_t)k * HIDc, ad2, lane);
            if (lane == 0) g_ud2[k] = s;
        }
    } else {
        int g = (b - IB_EAP - IB_W2 - IB_CNT - IB_US2) * 8 + (t >> 5);  // 0..95
        int lane = t & 31;
        if (g < 44) {                       // aev1[h][d]
            int h = g / EDD, d = g % EDD;
            float s = 0.f;
#pragma unroll
            for (int c = 0; c < 4; c++)
                s = fmaf(We1[d * D1 + h * HIDc + lane + 32 * c],
                         ae1[h * HIDc + lane + 32 * c], s);
            s = warp_red(s);
            if (lane == 0) g_aev1[g] = s;
        } else if (g < 55) {                // aev2[d]
            int d = g - 44;
            float s = warp_dot128(We2 + (size_t)d * HIDc, ae2, lane);
            if (lane == 0) g_aev2[d] = s;
        } else if (g < 75) {                // us1[h*5+d]
            int o = g - 55, h = o / IND, d = o % IND;
            float s = 0.f;
#pragma unroll
            for (int c = 0; c < 4; c++)
                s = fmaf(W1[d * D1 + h * HIDc + lane + 32 * c],
                         as1[h * HIDc + lane + 32 * c], s);
            s = warp_red(s);
            if (lane == 0) g_us1[o] = s;
        } else if (g < 95) {                // ud1[h*5+d]
            int o = g - 75, h = o / IND, d = o % IND;
            float s = 0.f;
#pragma unroll
            for (int c = 0; c < 4; c++)
                s = fmaf(W1[d * D1 + h * HIDc + lane + 32 * c],
                         ad1[h * HIDc + lane + 32 * c], s);
            s = warp_red(s);
            if (lane == 0) g_ud1[o] = s;
        }
    }
}

// fused: decoupled-lookback scan (blocks 0..156) | eamean (157) | node1 (158+)
__global__ void k_mid(const float* __restrict__ x) {
    int b = blockIdx.x, t = threadIdx.x;
    if (b < SC_BLOCKS) {
        int i = b * 256 + t;
        int v = (i < Nn) ? g_deg[i] : 0;
        int tot;
        int incl = block_scan_incl(v, t, &tot);
        __shared__ int s_off;
        volatile int* flag = g_flag;
        volatile int* aggv = g_aggv;
        volatile int* inclv = g_inclv;
        if (t == 0) {
            if (b == 0) {
                inclv[0] = tot; __threadfence(); flag[0] = 2;
                s_off = 0;
            } else {
                aggv[b] = tot; __threadfence(); flag[b] = 1;
                int run = 0, j = b - 1;
                while (true) {
                    int f;
                    do { f = flag[j]; } while (f == 0);
                    if (f == 2) { run += inclv[j]; break; }
                    run += aggv[j]; j--;
                }
                inclv[b] = run + tot; __threadfence(); flag[b] = 2;
                s_off = run;
            }
        }
        __syncthreads();
        int r = s_off + incl - v;
        if (i < Nn) { g_rowstart[i] = r; g_cursor[i] = r; }
        if (b == SC_BLOCKS - 1 && t == 255) g_rowstart[Nn] = ET;
    } else if (b == SC_BLOCKS) {
        int w = t >> 5, lane = t & 31;
        for (int col = w; col < EDD; col += 8) {
            float s = 0.f;
            for (int p = lane; p < EAP_BLOCKS; p += 32) s += g_eapart[p * EDD + col];
            s = warp_red(s);
            if (lane == 0) g_eamean[col] = s / (float)Ee;
        }
    } else {
        int idx = (b - SC_BLOCKS - 1) * 256 + t;
        int n = idx >> 3;
        if (n >= Nn) return;
        int r = idx & 7;
        int h = r & 3;
        const float* xp = x + (size_t)n * IND;
        g_x8[(size_t)n * 8 + r] = (r < IND) ? xp[r] : 0.f;
        const float* u = (r < 4) ? (g_us1 + h * IND) : (g_ud1 + h * IND);
        float s = 0.f;
#pragma unroll
        for (int d = 0; d < IND; d++) s += xp[d] * u[d];
        if (r < 4) g_as1[n * H1c + h] = s;
        else       g_ad1[n * H1c + h] = s;
    }
}

__global__ void k_scatter(const int* __restrict__ ei, const float* __restrict__ ea) {
    int e = blockIdx.x * blockDim.x + threadIdx.x;
    if (e >= ET) return;
    int s, d;
    float v[EDD];
    if (e < Ee) {
        s = ei[e]; d = ei[Ee + e];
        const float* p = ea + (size_t)e * EDD;
#pragma unroll
        for (int k = 0; k < EDD; k++) v[k] = p[k];
    } else {
        s = e - Ee; d = s;
#pragma unroll
        for (int k = 0; k < EDD; k++) v[k] = g_eamean[k];
    }
    int pos = atomicAdd(&g_cursor[d], 1);
    float e2 = 0.f;
#pragma unroll
    for (int k = 0; k < EDD; k++) e2 += v[k] * g_aev2[k];

    float4 asv = *(const float4*)&g_as1[s * H1c];
    float4 adv = *(const float4*)&g_ad1[d * H1c];
    float al[H1c];
#pragma unroll
    for (int h = 0; h < H1c; h++) {
        float ed = 0.f;
#pragma unroll
        for (int k = 0; k < EDD; k++) ed += v[k] * g_aev1[h * EDD + k];
        float a = ((h == 0) ? asv.x : (h == 1) ? asv.y : (h == 2) ? asv.z : asv.w)
                + ((h == 0) ? adv.x : (h == 1) ? adv.y : (h == 2) ? adv.z : adv.w) + ed;
        al[h] = (a > 0.f) ? a : NEG * a;
    }
    g_csr[(size_t)pos * 2]     = make_float4(__int_as_float(s), e2, al[0], al[1]);
    g_csr[(size_t)pos * 2 + 1] = make_float4(al[2], al[3], 0.f, 0.f);
}

// layer-1 softmax + aggregation + projection, three-phase (R12 form)
__global__ __launch_bounds__(256) void k_agg1(const float* __restrict__ W1,
                                              const float* __restrict__ b1) {
    __shared__ float s_ax[8][21];
    __shared__ uint32_t s_h1[8][256];       // bf16x2 packed, 8 KB
    __shared__ float s_u[D1];
    __shared__ float s_ud[D1];
    int t = threadIdx.x;
    int w = t >> 5, lane = t & 31;
    int n0 = blockIdx.x * 8;
    int n = n0 + w;                         // Nn % 8 == 0

#pragma unroll
    for (int i = 0; i < 2; i++) {
        s_u [t + i * 256] = g_us2[t + i * 256];
        s_ud[t + i * 256] = g_ud2[t + i * 256];
    }

    int base = g_rowstart[n];
    int deg  = g_rowstart[n + 1] - base;

    float den[H1c];
    float ax[H1c][IND];
#pragma unroll
    for (int h = 0; h < H1c; h++) {
        den[h] = 0.f;
#pragma unroll
        for (int d = 0; d < IND; d++) ax[h][d] = 0.f;
    }

    for (int i = lane; i < deg; i += 32) {
        float4 fa = g_csr[(size_t)(base + i) * 2];
        float4 fb = g_csr[(size_t)(base + i) * 2 + 1];
        int src = __float_as_int(fa.x);
        float e0 = __expf(fa.z), e1 = __expf(fa.w), e2 = __expf(fb.x), e3 = __expf(fb.y);
        den[0] += e0; den[1] += e1; den[2] += e2; den[3] += e3;
        const float* xp = g_x8 + (size_t)src * 8;
        float4 xv4 = __ldg((const float4*)xp);
        float xv5 = __ldg(xp + 4);
        float xv[IND] = {xv4.x, xv4.y, xv4.z, xv4.w, xv5};
#pragma unroll
        for (int d = 0; d < IND; d++) {
            ax[0][d] = fmaf(e0, xv[d], ax[0][d]);
            ax[1][d] = fmaf(e1, xv[d], ax[1][d]);
            ax[2][d] = fmaf(e2, xv[d], ax[2][d]);
            ax[3][d] = fmaf(e3, xv[d], ax[3][d]);
        }
    }
#pragma unroll
    for (int off = 16; off > 0; off >>= 1) {
#pragma unroll
        for (int h = 0; h < H1c; h++) {
            den[h] += __shfl_xor_sync(0xffffffffu, den[h], off);
#pragma unroll
            for (int d = 0; d < IND; d++)
                ax[h][d] += __shfl_xor_sync(0xffffffffu, ax[h][d], off);
        }
    }
    if (lane < 20) {
        int h = lane / IND, d = lane % IND;
        s_ax[w][lane] = ax[h][d] * (1.f / (den[h] + 1e-16f));
    }
    __syncthreads();

    int c0 = t * 2;
    int h2 = c0 >> 7;
    float2 wv[IND];
#pragma unroll
    for (int d = 0; d < IND; d++) wv[d] = *(const float2*)&W1[d * D1 + c0];
    float2 bb = *(const float2*)&b1[c0];

#pragma unroll
    for (int q = 0; q < 8; q++) {
        float a0 = bb.x, a1 = bb.y;
#pragma unroll
        for (int d = 0; d < IND; d++) {
            float av = s_ax[q][h2 * IND + d];
            a0 = fmaf(av, wv[d].x, a0);
            a1 = fmaf(av, wv[d].y, a1);
        }
        a0 = (a0 > 0.f) ? a0 : 0.f;
        a1 = (a1 > 0.f) ? a1 : 0.f;
        __nv_bfloat162 bv = __float22bfloat162_rn(make_float2(a0, a1));
        *(__nv_bfloat162*)(g_h1b + (size_t)(n0 + q) * D1 + c0) = bv;
        s_h1[q][t] = *(uint32_t*)&bv;
    }
    __syncthreads();

    float s2 = 0.f, d2v = 0.f;
#pragma unroll
    for (int j = 0; j < 8; j++) {
        int c = j * 32 + lane;
        uint32_t raw = s_h1[w][c];
        float2 f = __bfloat1622float2(*(__nv_bfloat162*)&raw);
        s2  = fmaf(f.x, s_u [2 * c], fmaf(f.y, s_u [2 * c + 1], s2));
        d2v = fmaf(f.x, s_ud[2 * c], fmaf(f.y, s_ud[2 * c + 1], d2v));
    }
    s2  = warp_red(s2);
    d2v = warp_red(d2v);
    if (lane == 0) { g_as2[n] = s2; g_ad2[n] = d2v; }
}

// xh2 = h1 @ W2 : bf16 wmma (HMMA), 128x128 CTA tile, K chunks of 64,
// cp.async double-buffered; bf16x2 packed output staged through smem.
#define KC 64
#define A_ELEMS 9216    /* 128 * 72 */
#define B_ELEMS 8704    /* 64 * 136 */
#define A_BYTES 18432
#define B_BYTES 17408
#define GSM_TOTAL (2 * (A_BYTES + B_BYTES))   /* 71680 >= 65536 for C staging */

__global__ __launch_bounds__(256, 2) void k_gemm() {
    extern __shared__ char smc[];
    __nv_bfloat16* As = (__nv_bfloat16*)smc;                     // [2][128][72]
    __nv_bfloat16* Bs = (__nv_bfloat16*)(smc + 2 * A_BYTES);     // [2][64][136]
    uint32_t smA = smem_u32(As);
    uint32_t smB = smem_u32(Bs);

    int t = threadIdx.x;
    int wid = t >> 5;
    int row0 = blockIdx.x * 128;
    int wm0 = (wid >> 2) * 64;     // 0 or 64
    int wn0 = (wid & 3) * 32;      // 0,32,64,96

    wmma::fragment<wmma::accumulator, 16, 16, 16, float> acc[4][2];
#pragma unroll
    for (int m = 0; m < 4; m++)
#pragma unroll
        for (int n = 0; n < 2; n++) wmma::fill_fragment(acc[m][n], 0.f);

    auto load_chunk = [&](int buf, int k0) {
#pragma unroll
        for (int i = 0; i < 4; i++) {
            int v = i * 256 + t;
            int r = v >> 3, c8 = v & 7;                 // A: 128 rows x 8 uint4
            cp_async16(smA + (uint32_t)(buf * A_ELEMS + r * 72 + c8 * 8) * 2,
                       g_h1b + (size_t)(row0 + r) * D1 + k0 + c8 * 8);
        }
#pragma unroll
        for (int i = 0; i < 4; i++) {
            int v = i * 256 + t;
            int r = v >> 4, c8 = v & 15;                // B: 64 rows x 16 uint4
            cp_async16(smB + (uint32_t)(buf * B_ELEMS + r * 136 + c8 * 8) * 2,
                       g_W2b + (size_t)(k0 + r) * HIDc + c8 * 8);
        }
        CP_COMMIT();
    };

    load_chunk(0, 0);
    int buf = 0;
#pragma unroll
    for (int c = 0; c < 8; c++) {
        if (c < 7) load_chunk(buf ^ 1, (c + 1) * KC);
        if (c < 7) CP_WAIT1(); else CP_WAIT0();
        __syncthreads();

        const __nv_bfloat16* Ab = As + buf * A_ELEMS;
        const __nv_bfloat16* Bb = Bs + buf * B_ELEMS;
#pragma unroll
        for (int kk = 0; kk < 4; kk++) {
            wmma::fragment<wmma::matrix_a, 16, 16, 16, __nv_bfloat16, wmma::row_major> af[4];
            wmma::fragment<wmma::matrix_b, 16, 16, 16, __nv_bfloat16, wmma::row_major> bf[2];
#pragma unroll
            for (int m = 0; m < 4; m++)
                wmma::load_matrix_sync(af[m], Ab + (wm0 + m * 16) * 72 + kk * 16, 72);
#pragma unroll
            for (int n = 0; n < 2; n++)
                wmma::load_matrix_sync(bf[n], Bb + (kk * 16) * 136 + wn0 + n * 16, 136);
#pragma unroll
            for (int m = 0; m < 4; m++)
#pragma unroll
                for (int n = 0; n < 2; n++)
                    wmma::mma_sync(acc[m][n], af[m], bf[n], acc[m][n]);
        }
        __syncthreads();
        buf ^= 1;
    }

    // stage fp32 C in smem, emit packed bf16x2
    float* Cs = (float*)smc;    // 128*128 fp32 = 64KB
#pragma unroll
    for (int m = 0; m < 4; m++)
#pragma unroll
        for (int n = 0; n < 2; n++)
            wmma::store_matrix_sync(Cs + (size_t)(wm0 + m * 16) * 128 + wn0 + n * 16,
                                    acc[m][n], 128, wmma::mem_row_major);
    __syncthreads();
#pragma unroll
    for (int j = 0; j < 32; j++) {
        int idx = j * 256 + t;          // 8192 bf16x2 pairs
        int row = idx >> 6, cp = idx & 63;
        float2 f = *(const float2*)&Cs[row * 128 + cp * 2];
        __nv_bfloat162 bv = __float22bfloat162_rn(f);
        g_xh2b[(size_t)(row0 + row) * 64 + cp] = *(uint32_t*)&bv;
    }
}

// layer-2 softmax + aggregation + final linear + sigmoid, warp-per-node.
// No block barriers: per-lane edge registers + shfl broadcast gather.
__global__ __launch_bounds__(256) void k_agg2(const float* __restrict__ b2,
                                              const float* __restrict__ Wfc,
                                              const float* __restrict__ bfc,
                                              float* __restrict__ out) {
    int t = threadIdx.x;
    int w = t >> 5, lane = t & 31;
    int n = blockIdx.x * 8 + w;            // Nn % 8 == 0
    int base = g_rowstart[n];
    int deg  = g_rowstart[n + 1] - base;
    float ad = g_ad2[n];

    float acc0 = 0.f, acc1 = 0.f, acc2 = 0.f, acc3 = 0.f;
    float den = 0.f;

    for (int b0 = 0; b0 < deg; b0 += 32) {
        float ex = 0.f; int src = 0;
        int i = b0 + lane;
        if (i < deg) {
            float4 f = g_csr[(size_t)(base + i) * 2];
            src = __float_as_int(f.x);
            float al = g_as2[src] + ad + f.y;
            al = (al > 0.f) ? al : NEG * al;
            ex = __expf(al);
        }
        den += ex;
        int cnt = deg - b0; if (cnt > 32) cnt = 32;
        for (int j = 0; j < cnt; j++) {
            float exj = __shfl_sync(0xffffffffu, ex, j);
            int srcj  = __shfl_sync(0xffffffffu, src, j);
            uint2 raw = *(const uint2*)&g_xh2b[(size_t)srcj * 64 + lane * 2];
            float2 f0 = __bfloat1622float2(*(__nv_bfloat162*)&raw.x);
            float2 f1 = __bfloat1622float2(*(__nv_bfloat162*)&raw.y);
            acc0 = fmaf(exj, f0.x, acc0);
            acc1 = fmaf(exj, f0.y, acc1);
            acc2 = fmaf(exj, f1.x, acc2);
            acc3 = fmaf(exj, f1.y, acc3);
        }
    }
#pragma unroll
    for (int off = 16; off > 0; off >>= 1)
        den += __shfl_xor_sync(0xffffffffu, den, off);
    float inv = 1.f / (den + 1e-16f);

    float4 bb = *(const float4*)&b2[lane * 4];
    float4 wf = *(const float4*)&Wfc[lane * 4];
    float h0 = acc0 * inv + bb.x; h0 = (h0 > 0.f) ? h0 : 0.f;
    float h1 = acc1 * inv + bb.y; h1 = (h1 > 0.f) ? h1 : 0.f;
    float h2 = acc2 * inv + bb.z; h2 = (h2 > 0.f) ? h2 : 0.f;
    float h3 = acc3 * inv + bb.w; h3 = (h3 > 0.f) ? h3 : 0.f;
    float part = fmaf(h0, wf.x, fmaf(h1, wf.y, fmaf(h2, wf.z, h3 * wf.w)));
    part = warp_red(part);
    if (lane == 0) {
        float z = part + bfc[0];
        out[n] = 1.f / (1.f + __expf(-z));
    }
}

// ---------------- launcher -------------------------------------------------

extern "C" void kernel_launch(void* const* d_in, const int* in_sizes, int n_in,
                              void* d_out, int out_size) {
    const float* x    = (const float*)d_in[0];
    const int*   ei   = (const int*)  d_in[1];
    const float* ea   = (const float*)d_in[2];
    const float* W1   = (const float*)d_in[3];
    const float* We1  = (const float*)d_in[4];
    const float* as1v = (const float*)d_in[5];
    const float* ad1v = (const float*)d_in[6];
    const float* ae1v = (const float*)d_in[7];
    const float* b1   = (const float*)d_in[8];
    const float* W2   = (const float*)d_in[9];
    const float* We2  = (const float*)d_in[10];
    const float* as2v = (const float*)d_in[11];
    const float* ad2v = (const float*)d_in[12];
    const float* ae2v = (const float*)d_in[13];
    const float* b2   = (const float*)d_in[14];
    const float* Wfc  = (const float*)d_in[15];
    const float* bfc  = (const float*)d_in[16];
    float* out = (float*)d_out;

    static void* p_deg = nullptr;
    static void* p_flag = nullptr;
    if (!p_deg) {
        cudaFuncSetAttribute(k_gemm, cudaFuncAttributeMaxDynamicSharedMemorySize, GSM_TOTAL);
        cudaGetSymbolAddress(&p_deg, g_deg);
        cudaGetSymbolAddress(&p_flag, g_flag);
    }

    cudaMemsetAsync(p_deg, 0, Nn * sizeof(int));
    cudaMemsetAsync(p_flag, 0, SC_BLOCKS * sizeof(int));
    k_init<<<IB_TOTAL, 256>>>(ea, W2, ei, W1, We1, We2,
                              as1v, ad1v, ae1v, as2v, ad2v, ae2v);
    k_mid<<<SC_BLOCKS + 1 + N1_BLOCKS, 256>>>(x);
    k_scatter<<<(ET + 255) / 256, 256>>>(ei, ea);
    k_agg1<<<Nn / 8, 256>>>(W1, b1);
    k_gemm<<<MROWS / 128, 256, GSM_TOTAL>>>();
    k_agg2<<<Nn / 8, 256>>>(b2, Wfc, bfc, out);
}